// round 2
// baseline (speedup 1.0000x reference)
#include <cuda_runtime.h>
#include <cuda_bf16.h>
#include <cstdint>

// Problem constants
#define NWIN 400    // 4 * 10 * 10 windows
#define NTOK 324    // 18*18 tokens per window
#define NPAD 336    // tokens padded to multiple of 16 (and of 8)
#define CE   128    // embed channels
#define CC   256    // channels
#define HH   180
#define WSZ  18
#define XW_LD 344   // padded smem row stride for xw (bank-conflict relief)

// ---------------- global scratch (static __device__, no allocation) ----------------
__device__ __nv_bfloat16 g_theta[NWIN * NPAD * CE];   // [w][n][e]
__device__ __nv_bfloat16 g_phi  [NWIN * CE * NPAD];   // [w][e][n]
__device__ __nv_bfloat16 g_xwT  [NWIN * NPAD * CC];   // [w][n][c]
__device__ __nv_bfloat16 g_wcomb [CC * CC];           // [e][c], e<128 theta, e>=128 phi
__device__ __nv_bfloat16 g_wprojT[CC * CC];           // [c][o]

// ---------------- mma helpers (m16n8k16 bf16, direct fragment loads) ----------------
__device__ __forceinline__ uint32_t lda32(const __nv_bfloat16* p) {
    return *reinterpret_cast<const uint32_t*>(p);
}
// pack B[k][n], B[k+1][n] from row-major [k][n] smem (k-strided)
__device__ __forceinline__ uint32_t ldb_pack(const __nv_bfloat16* base, int k, int n, int ld) {
    uint32_t lo = *reinterpret_cast<const uint16_t*>(base + k * ld + n);
    uint32_t hi = *reinterpret_cast<const uint16_t*>(base + (k + 1) * ld + n);
    return lo | (hi << 16);
}
__device__ __forceinline__ void mma16816(float* c, uint32_t a0, uint32_t a1,
                                         uint32_t a2, uint32_t a3,
                                         uint32_t b0, uint32_t b1) {
    asm volatile(
        "mma.sync.aligned.m16n8k16.row.col.f32.bf16.bf16.f32 "
        "{%0,%1,%2,%3},{%4,%5,%6,%7},{%8,%9},{%0,%1,%2,%3};\n"
        : "+f"(c[0]), "+f"(c[1]), "+f"(c[2]), "+f"(c[3])
        : "r"(a0), "r"(a1), "r"(a2), "r"(a3), "r"(b0), "r"(b1));
}

// ---------------- kernel 1: weight prep (combined embed weight + proj transpose) ----
__global__ void prep_kernel(const float* __restrict__ wt, const float* __restrict__ wp,
                            const float* __restrict__ wproj) {
    int idx = blockIdx.x * blockDim.x + threadIdx.x;
    if (idx < CC * CC) {
        int r = idx >> 8, c = idx & 255;
        float v = (r < CE) ? wt[r * CC + c] : wp[(r - CE) * CC + c];
        g_wcomb[idx] = __float2bfloat16(v);
        // wprojT[c_in][o] = wproj[o][c_in]  (here r = c_in, c = o)
        g_wprojT[r * CC + c] = __float2bfloat16(wproj[c * CC + r]);
    }
}

// ---------------- kernel 2: window partition + embed GEMM ----------------
// smem: xw_s [256][XW_LD] bf16 + wchunk [64][64] bf16
#define EMBED_SMEM (CC * XW_LD * 2 + 64 * 64 * 2)

__global__ __launch_bounds__(256, 1) void embed_kernel(const float* __restrict__ x) {
    extern __shared__ char smem_raw[];
    __nv_bfloat16* xw_s   = reinterpret_cast<__nv_bfloat16*>(smem_raw);          // [c][n] ld=XW_LD
    __nv_bfloat16* wchunk = xw_s + CC * XW_LD;                                    // [64][64]

    int w = blockIdx.x;
    int b = w / 100, rem = w % 100, wh = rem / 10, ww = rem % 10;
    int h0 = wh * WSZ, w0 = ww * WSZ;
    const float* xb = x + (size_t)b * CC * HH * HH;
    int tid = threadIdx.x;

    // load window into smem (bf16), zero-pad n in [324,336)
    for (int idx = tid; idx < CC * NPAD; idx += 256) {
        int c = idx / NPAD, n = idx - c * NPAD;
        float v = 0.f;
        if (n < NTOK) {
            int i = n / WSZ, j = n - i * WSZ;
            v = xb[(c * HH + h0 + i) * HH + w0 + j];
        }
        xw_s[c * XW_LD + n] = __float2bfloat16(v);
    }
    __syncthreads();

    // write token-major copy xwT[w][n][c]
    __nv_bfloat16* xwT = g_xwT + (size_t)w * NPAD * CC;
    for (int idx = tid; idx < NPAD * CC; idx += 256) {
        int n = idx >> 8, c = idx & 255;
        xwT[idx] = xw_s[c * XW_LD + n];
    }

    int warp = tid >> 5, lane = tid & 31;
    int rw = warp >> 1, cw = warp & 1;     // 4 row-groups x 2 col-halves
    int g = lane >> 2, q = lane & 3;

    __nv_bfloat16* th = g_theta + (size_t)w * NPAD * CE;
    __nv_bfloat16* ph = g_phi   + (size_t)w * CE * NPAD;

    for (int eb = 0; eb < 4; eb++) {       // 4 blocks of 64 output rows (e)
        float acc[21][4];
        #pragma unroll
        for (int t = 0; t < 21; t++) { acc[t][0]=0.f; acc[t][1]=0.f; acc[t][2]=0.f; acc[t][3]=0.f; }

        for (int kc = 0; kc < 4; kc++) {   // k chunks of 64
            for (int idx = tid; idx < 64 * 64; idx += 256) {
                int e = idx >> 6, k = idx & 63;
                wchunk[idx] = g_wcomb[(eb * 64 + e) * CC + kc * 64 + k];
            }
            __syncthreads();
            #pragma unroll
            for (int kt = 0; kt < 4; kt++) {
                int ar = rw * 16 + g;
                int ak = kt * 16 + q * 2;
                uint32_t a0 = lda32(&wchunk[ar * 64 + ak]);
                uint32_t a1 = lda32(&wchunk[(ar + 8) * 64 + ak]);
                uint32_t a2 = lda32(&wchunk[ar * 64 + ak + 8]);
                uint32_t a3 = lda32(&wchunk[(ar + 8) * 64 + ak + 8]);
                int kg = kc * 64 + kt * 16 + q * 2;
                #pragma unroll
                for (int t = 0; t < 21; t++) {
                    int ncol = cw * 168 + t * 8 + g;
                    uint32_t b0 = ldb_pack(xw_s, kg,     ncol, XW_LD);
                    uint32_t b1 = ldb_pack(xw_s, kg + 8, ncol, XW_LD);
                    mma16816(acc[t], a0, a1, a2, a3, b0, b1);
                }
            }
            __syncthreads();
        }
        // store: theta transposed [n][e], phi natural [e][n]
        #pragma unroll
        for (int t = 0; t < 21; t++) {
            int n = cw * 168 + t * 8 + q * 2;
            int e0 = eb * 64 + rw * 16 + g;
            int e1 = e0 + 8;
            __nv_bfloat16 v0 = __float2bfloat16(acc[t][0]);
            __nv_bfloat16 v1 = __float2bfloat16(acc[t][1]);
            __nv_bfloat16 v2 = __float2bfloat16(acc[t][2]);
            __nv_bfloat16 v3 = __float2bfloat16(acc[t][3]);
            if (e0 < CE) { th[n * CE + e0] = v0; th[(n + 1) * CE + e0] = v1; }
            else         { ph[(e0 - CE) * NPAD + n] = v0; ph[(e0 - CE) * NPAD + n + 1] = v1; }
            if (e1 < CE) { th[n * CE + e1] = v2; th[(n + 1) * CE + e1] = v3; }
            else         { ph[(e1 - CE) * NPAD + n] = v2; ph[(e1 - CE) * NPAD + n + 1] = v3; }
        }
    }
}

// ---------------- kernel 3: fused attention + projection + residual ----------------
// smem layout (bf16 elems unless noted):
//   phi_s  [128][336]  86016 B
//   P_s    [64][336]   43008 B
//   th_s   [64][128]   16384 B
//   y_s    [64][256]   32768 B
//   chunk  [64][256]   32768 B   (also reused as out_s: fp32 [64][65] = 16640 B)
//   stats_max [64][2] f32, stats_sum [64][2] f32
#define ATTN_SMEM ((CE*NPAD + 64*NPAD + 64*CE + 64*CC + 64*CC) * 2 + 64*2*4 + 64*2*4)

__global__ __launch_bounds__(256, 1) void attn_kernel(const float* __restrict__ x,
                                                      float* __restrict__ out) {
    extern __shared__ char smem_raw[];
    __nv_bfloat16* phi_s = reinterpret_cast<__nv_bfloat16*>(smem_raw);
    __nv_bfloat16* P_s   = phi_s + CE * NPAD;
    __nv_bfloat16* th_s  = P_s + 64 * NPAD;
    __nv_bfloat16* y_s   = th_s + 64 * CE;
    __nv_bfloat16* chunk = y_s + 64 * CC;
    float* stats_max = reinterpret_cast<float*>(chunk + 64 * CC);
    float* stats_sum = stats_max + 64 * 2;
    float* out_s = reinterpret_cast<float*>(chunk);   // reuse, fp32 [64][65]

    int w = blockIdx.x;
    int b = w / 100, rem = w % 100, wh = rem / 10, ww = rem % 10;
    int h0 = wh * WSZ, w0 = ww * WSZ;
    int tid = threadIdx.x;
    int warp = tid >> 5, lane = tid & 31;
    int rw = warp >> 1, cw = warp & 1;
    int g = lane >> 2, q = lane & 3;

    const __nv_bfloat16* thg = g_theta + (size_t)w * NPAD * CE;
    const __nv_bfloat16* phg = g_phi   + (size_t)w * CE * NPAD;
    const __nv_bfloat16* xwT = g_xwT   + (size_t)w * NPAD * CC;

    // load phi into smem once per window
    for (int idx = tid; idx < CE * NPAD; idx += 256) phi_s[idx] = phg[idx];
    __syncthreads();

    const float scale = 0.08838834764831845f;  // 1/sqrt(128)

    for (int blk = 0; blk < 6; blk++) {        // 6 blocks of 64 token rows (384 >= 336)
        // ---- stage theta rows for this block ----
        for (int idx = tid; idx < 64 * CE; idx += 256) {
            int r = idx >> 7, k = idx & 127;
            int ng = blk * 64 + r;
            th_s[idx] = (ng < NPAD) ? thg[ng * CE + k] : __float2bfloat16(0.f);
        }
        __syncthreads();

        // ---- S = theta_blk @ phi (64x336), k=128, in registers ----
        float sacc[21][4];
        #pragma unroll
        for (int t = 0; t < 21; t++) { sacc[t][0]=0.f; sacc[t][1]=0.f; sacc[t][2]=0.f; sacc[t][3]=0.f; }
        #pragma unroll
        for (int kt = 0; kt < 8; kt++) {
            int ar = rw * 16 + g;
            int ak = kt * 16 + q * 2;
            uint32_t a0 = lda32(&th_s[ar * CE + ak]);
            uint32_t a1 = lda32(&th_s[(ar + 8) * CE + ak]);
            uint32_t a2 = lda32(&th_s[ar * CE + ak + 8]);
            uint32_t a3 = lda32(&th_s[(ar + 8) * CE + ak + 8]);
            #pragma unroll
            for (int t = 0; t < 21; t++) {
                int ncol = cw * 168 + t * 8 + g;
                uint32_t b0 = ldb_pack(phi_s, ak,     ncol, NPAD);
                uint32_t b1 = ldb_pack(phi_s, ak + 8, ncol, NPAD);
                mma16816(sacc[t], a0, a1, a2, a3, b0, b1);
            }
        }
        // ---- scale + column mask ----
        #pragma unroll
        for (int t = 0; t < 21; t++) {
            int c0 = cw * 168 + t * 8 + q * 2;
            #pragma unroll
            for (int i = 0; i < 4; i++) {
                float v = sacc[t][i] * scale;
                int col = c0 + (i & 1);
                if (col >= NTOK) v = -1e30f;
                sacc[t][i] = v;
            }
        }
        // ---- row max (2 rows per thread) ----
        float m0 = -1e30f, m1 = -1e30f;
        #pragma unroll
        for (int t = 0; t < 21; t++) {
            m0 = fmaxf(m0, fmaxf(sacc[t][0], sacc[t][1]));
            m1 = fmaxf(m1, fmaxf(sacc[t][2], sacc[t][3]));
        }
        m0 = fmaxf(m0, __shfl_xor_sync(0xffffffffu, m0, 1));
        m0 = fmaxf(m0, __shfl_xor_sync(0xffffffffu, m0, 2));
        m1 = fmaxf(m1, __shfl_xor_sync(0xffffffffu, m1, 1));
        m1 = fmaxf(m1, __shfl_xor_sync(0xffffffffu, m1, 2));
        int row0 = rw * 16 + g, row1 = row0 + 8;
        if (q == 0) { stats_max[row0 * 2 + cw] = m0; stats_max[row1 * 2 + cw] = m1; }
        __syncthreads();
        float rmax0 = fmaxf(stats_max[row0 * 2], stats_max[row0 * 2 + 1]);
        float rmax1 = fmaxf(stats_max[row1 * 2], stats_max[row1 * 2 + 1]);
        // ---- exp + row sums ----
        float s0 = 0.f, s1 = 0.f;
        #pragma unroll
        for (int t = 0; t < 21; t++) {
            sacc[t][0] = __expf(sacc[t][0] - rmax0);
            sacc[t][1] = __expf(sacc[t][1] - rmax0);
            sacc[t][2] = __expf(sacc[t][2] - rmax1);
            sacc[t][3] = __expf(sacc[t][3] - rmax1);
            s0 += sacc[t][0] + sacc[t][1];
            s1 += sacc[t][2] + sacc[t][3];
        }
        s0 += __shfl_xor_sync(0xffffffffu, s0, 1);
        s0 += __shfl_xor_sync(0xffffffffu, s0, 2);
        s1 += __shfl_xor_sync(0xffffffffu, s1, 1);
        s1 += __shfl_xor_sync(0xffffffffu, s1, 2);
        if (q == 0) { stats_sum[row0 * 2 + cw] = s0; stats_sum[row1 * 2 + cw] = s1; }
        __syncthreads();
        float inv0 = 1.f / (stats_sum[row0 * 2] + stats_sum[row0 * 2 + 1]);
        float inv1 = 1.f / (stats_sum[row1 * 2] + stats_sum[row1 * 2 + 1]);
        // ---- write normalized P (bf16) ----
        #pragma unroll
        for (int t = 0; t < 21; t++) {
            int c0 = cw * 168 + t * 8 + q * 2;
            P_s[row0 * NPAD + c0]     = __float2bfloat16(sacc[t][0] * inv0);
            P_s[row0 * NPAD + c0 + 1] = __float2bfloat16(sacc[t][1] * inv0);
            P_s[row1 * NPAD + c0]     = __float2bfloat16(sacc[t][2] * inv1);
            P_s[row1 * NPAD + c0 + 1] = __float2bfloat16(sacc[t][3] * inv1);
        }
        __syncthreads();

        // ---- y = P @ xwT  (64x256), k=336 in 7 chunks of 48 ----
        float yacc[16][4];
        #pragma unroll
        for (int t = 0; t < 16; t++) { yacc[t][0]=0.f; yacc[t][1]=0.f; yacc[t][2]=0.f; yacc[t][3]=0.f; }
        for (int kc = 0; kc < 7; kc++) {
            for (int idx = tid; idx < 48 * CC; idx += 256) {
                int kk = idx >> 8, c = idx & 255;
                chunk[idx] = xwT[(kc * 48 + kk) * CC + c];
            }
            __syncthreads();
            #pragma unroll
            for (int kt = 0; kt < 3; kt++) {
                int ar = rw * 16 + g;
                int akg = kc * 48 + kt * 16 + q * 2;   // k in P
                int akl = kt * 16 + q * 2;             // k in chunk
                uint32_t a0 = lda32(&P_s[ar * NPAD + akg]);
                uint32_t a1 = lda32(&P_s[(ar + 8) * NPAD + akg]);
                uint32_t a2 = lda32(&P_s[ar * NPAD + akg + 8]);
                uint32_t a3 = lda32(&P_s[(ar + 8) * NPAD + akg + 8]);
                #pragma unroll
                for (int t = 0; t < 16; t++) {
                    int ncol = cw * 128 + t * 8 + g;
                    uint32_t b0 = ldb_pack(chunk, akl,     ncol, CC);
                    uint32_t b1 = ldb_pack(chunk, akl + 8, ncol, CC);
                    mma16816(yacc[t], a0, a1, a2, a3, b0, b1);
                }
            }
            __syncthreads();
        }
        // ---- stage y (bf16) ----
        {
            int r0 = rw * 16 + g, r1 = r0 + 8;
            #pragma unroll
            for (int t = 0; t < 16; t++) {
                int c0 = cw * 128 + t * 8 + q * 2;
                y_s[r0 * CC + c0]     = __float2bfloat16(yacc[t][0]);
                y_s[r0 * CC + c0 + 1] = __float2bfloat16(yacc[t][1]);
                y_s[r1 * CC + c0]     = __float2bfloat16(yacc[t][2]);
                y_s[r1 * CC + c0 + 1] = __float2bfloat16(yacc[t][3]);
            }
        }
        __syncthreads();

        // ---- outp = y @ wprojT (64x256), k=256 in 4 chunks of 64 ----
        float pacc[16][4];
        #pragma unroll
        for (int t = 0; t < 16; t++) { pacc[t][0]=0.f; pacc[t][1]=0.f; pacc[t][2]=0.f; pacc[t][3]=0.f; }
        for (int kc = 0; kc < 4; kc++) {
            for (int idx = tid; idx < 64 * CC; idx += 256) {
                int kk = idx >> 8, o = idx & 255;
                chunk[idx] = g_wprojT[(kc * 64 + kk) * CC + o];
            }
            __syncthreads();
            #pragma unroll
            for (int kt = 0; kt < 4; kt++) {
                int ar = rw * 16 + g;
                int akg = kc * 64 + kt * 16 + q * 2;   // k in y_s
                int akl = kt * 16 + q * 2;             // k in chunk
                uint32_t a0 = lda32(&y_s[ar * CC + akg]);
                uint32_t a1 = lda32(&y_s[(ar + 8) * CC + akg]);
                uint32_t a2 = lda32(&y_s[ar * CC + akg + 8]);
                uint32_t a3 = lda32(&y_s[(ar + 8) * CC + akg + 8]);
                #pragma unroll
                for (int t = 0; t < 16; t++) {
                    int ncol = cw * 128 + t * 8 + g;
                    uint32_t b0 = ldb_pack(chunk, akl,     ncol, CC);
                    uint32_t b1 = ldb_pack(chunk, akl + 8, ncol, CC);
                    mma16816(pacc[t], a0, a1, a2, a3, b0, b1);
                }
            }
            __syncthreads();
        }

        // ---- epilogue: transpose via smem, residual add, coalesced write ----
        for (int oc = 0; oc < 4; oc++) {     // 4 column chunks of 64 channels
            if ((oc >> 1) == cw) {
                int tb = (oc & 1) * 8;
                int r0 = rw * 16 + g, r1 = r0 + 8;
                #pragma unroll
                for (int t = 0; t < 8; t++) {
                    int cl = t * 8 + q * 2;
                    out_s[r0 * 65 + cl]     = pacc[tb + t][0];
                    out_s[r0 * 65 + cl + 1] = pacc[tb + t][1];
                    out_s[r1 * 65 + cl]     = pacc[tb + t][2];
                    out_s[r1 * 65 + cl + 1] = pacc[tb + t][3];
                }
            }
            __syncthreads();
            for (int idx = tid; idx < 64 * 64; idx += 256) {
                int ol = idx >> 6, nl = idx & 63;
                int ng = blk * 64 + nl;
                if (ng < NTOK) {
                    int o = oc * 64 + ol;
                    int i = ng / WSZ, j = ng - i * WSZ;
                    size_t gi = ((size_t)(b * CC + o) * HH + h0 + i) * HH + w0 + j;
                    out[gi] = x[gi] + out_s[nl * 65 + ol];
                }
            }
            __syncthreads();
        }
    }
}

// ---------------- launch ----------------
extern "C" void kernel_launch(void* const* d_in, const int* in_sizes, int n_in,
                              void* d_out, int out_size) {
    const float* x     = (const float*)d_in[0];
    const float* wt    = (const float*)d_in[1];
    const float* wp    = (const float*)d_in[2];
    const float* wproj = (const float*)d_in[3];
    float* out = (float*)d_out;

    cudaFuncSetAttribute(embed_kernel, cudaFuncAttributeMaxDynamicSharedMemorySize, EMBED_SMEM);
    cudaFuncSetAttribute(attn_kernel,  cudaFuncAttributeMaxDynamicSharedMemorySize, ATTN_SMEM);

    prep_kernel<<<256, 256>>>(wt, wp, wproj);
    embed_kernel<<<NWIN, 256, EMBED_SMEM>>>(x);
    attn_kernel<<<NWIN, 256, ATTN_SMEM>>>(x, out);
}

// round 5
// speedup vs baseline: 1.4769x; 1.4769x over previous
#include <cuda_runtime.h>
#include <cuda_bf16.h>
#include <cstdint>

// Problem constants
#define NWIN 400    // 4 * 10 * 10 windows
#define NTOK 324    // 18*18 tokens per window
#define NPAD 336    // tokens padded to multiple of 16
#define CE   128    // embed channels
#define CC   256    // channels
#define HH   180
#define WSZ  18

// smem leading dims (elements); ld/2 mod 32 in {4,12,28} -> conflict-free g*k+q perms
#define EMB_LD 264  // 132 words, mod32=4
#define TH_LD  136  // 68 words,  mod32=4
#define P_LD   344  // 172 words, mod32=12
#define AV_LD  56   // 28 words,  mod32=28
#define PJ_LD  72   // 36 words,  mod32=4

// ---------------- global scratch (static __device__, no allocation) ----------------
__device__ __nv_bfloat16 g_embT [NWIN * NPAD * CC];  // [w][n][e]: e<128 theta, e>=128 phi
__device__ __nv_bfloat16 g_xw   [NWIN * CC * NPAD];  // [w][c][m] channel-major window
__device__ __nv_bfloat16 g_wcombb[CC * CC];          // [e][c] combined (theta rows, phi rows)
__device__ __nv_bfloat16 g_wprojb[CC * CC];          // [o][c] as stored

// ---------------- mma helpers ----------------
__device__ __forceinline__ uint32_t lda32(const __nv_bfloat16* p) {
    return *reinterpret_cast<const uint32_t*>(p);
}
__device__ __forceinline__ void mma16816(float* c, uint32_t a0, uint32_t a1,
                                         uint32_t a2, uint32_t a3,
                                         uint32_t b0, uint32_t b1) {
    asm volatile(
        "mma.sync.aligned.m16n8k16.row.col.f32.bf16.bf16.f32 "
        "{%0,%1,%2,%3},{%4,%5,%6,%7},{%8,%9},{%0,%1,%2,%3};\n"
        : "+f"(c[0]), "+f"(c[1]), "+f"(c[2]), "+f"(c[3])
        : "r"(a0), "r"(a1), "r"(a2), "r"(a3), "r"(b0), "r"(b1));
}
__device__ __forceinline__ void st_bf2(__nv_bfloat16* p, float lo, float hi) {
    __nv_bfloat162 v = __floats2bfloat162_rn(lo, hi);
    *reinterpret_cast<__nv_bfloat162*>(p) = v;
}

// ---------------- kernel 1: weight prep ----------------
__global__ void prep_kernel(const float* __restrict__ wt, const float* __restrict__ wp,
                            const float* __restrict__ wproj) {
    int idx = blockIdx.x * blockDim.x + threadIdx.x;
    if (idx < CC * CC) {
        int r = idx >> 8, c = idx & 255;
        float v = (r < CE) ? wt[r * CC + c] : wp[(r - CE) * CC + c];
        g_wcombb[idx] = __float2bfloat16(v);
        g_wprojb[idx] = __float2bfloat16(wproj[idx]);   // keep [o][c]
    }
}

// ---------------- kernel 2: window partition + embed GEMM ----------------
// smem: wcomb_s [256][EMB_LD] + xwT_blk [64][EMB_LD]
#define EMBED_SMEM ((CC * EMB_LD + 64 * EMB_LD) * 2)

__global__ __launch_bounds__(256, 1) void embed_kernel(const float* __restrict__ x) {
    extern __shared__ char smem_raw[];
    __nv_bfloat16* wcomb_s = reinterpret_cast<__nv_bfloat16*>(smem_raw);   // [e][c]
    __nv_bfloat16* xwT_blk = wcomb_s + CC * EMB_LD;                        // [n][c]

    int w = blockIdx.x;
    int b = w / 100, rem = w % 100, wh = rem / 10, ww = rem % 10;
    int h0 = wh * WSZ, w0 = ww * WSZ;
    const float* xb = x + (size_t)b * CC * HH * HH;
    int tid = threadIdx.x;
    int warp = tid >> 5, lane = tid & 31;
    int rw = warp >> 1, cw = warp & 1;
    int g = lane >> 2, q = lane & 3;

    // stage full combined weight once
    for (int idx = tid; idx < CC * CC; idx += 256) {
        int e = idx >> 8, c = idx & 255;
        wcomb_s[e * EMB_LD + c] = g_wcombb[idx];
    }

    __nv_bfloat16* xwg  = g_xw   + (size_t)w * CC * NPAD;
    __nv_bfloat16* embT = g_embT + (size_t)w * NPAD * CC;
    __syncthreads();

    for (int blk = 0; blk < 6; blk++) {       // 6 blocks of 64 token rows
        // build xwT_blk [64][256] from x; also emit channel-major g_xw
        for (int idx = tid; idx < 64 * CC; idx += 256) {
            int c = idx >> 6, nn = idx & 63;
            int m = blk * 64 + nn;
            float v = 0.f;
            if (m < NTOK) {
                int i = m / WSZ, j = m - i * WSZ;
                v = xb[((size_t)c * HH + h0 + i) * HH + w0 + j];
            }
            __nv_bfloat16 bv = __float2bfloat16(v);
            xwT_blk[nn * EMB_LD + c] = bv;
            if (m < NPAD) xwg[c * NPAD + m] = bv;
        }
        __syncthreads();

        // embT_blk = xwT_blk @ wcomb^T : [64][256], k=256
        float acc[16][4];
        #pragma unroll
        for (int t = 0; t < 16; t++) { acc[t][0]=0.f; acc[t][1]=0.f; acc[t][2]=0.f; acc[t][3]=0.f; }
        #pragma unroll
        for (int kt = 0; kt < 16; kt++) {
            int ar = rw * 16 + g;
            int ak = kt * 16 + q * 2;
            uint32_t a0 = lda32(&xwT_blk[ar * EMB_LD + ak]);
            uint32_t a1 = lda32(&xwT_blk[(ar + 8) * EMB_LD + ak]);
            uint32_t a2 = lda32(&xwT_blk[ar * EMB_LD + ak + 8]);
            uint32_t a3 = lda32(&xwT_blk[(ar + 8) * EMB_LD + ak + 8]);
            #pragma unroll
            for (int t = 0; t < 16; t++) {
                int ncol = cw * 128 + t * 8 + g;
                uint32_t b0 = lda32(&wcomb_s[ncol * EMB_LD + ak]);
                uint32_t b1 = lda32(&wcomb_s[ncol * EMB_LD + ak + 8]);
                mma16816(acc[t], a0, a1, a2, a3, b0, b1);
            }
        }
        // store token-major embeddings
        {
            int r0 = blk * 64 + rw * 16 + g, r1 = r0 + 8;
            #pragma unroll
            for (int t = 0; t < 16; t++) {
                int e0 = cw * 128 + t * 8 + q * 2;
                if (r0 < NPAD) st_bf2(&embT[r0 * CC + e0], acc[t][0], acc[t][1]);
                if (r1 < NPAD) st_bf2(&embT[r1 * CC + e0], acc[t][2], acc[t][3]);
            }
        }
        __syncthreads();
    }
}

// ---------------- kernel 3: fused attention + projection + residual ----------------
// smem: phi_sT [336][TH_LD], th_s [64][TH_LD], P_s [64][P_LD], y_s [64][EMB_LD],
//       chunk [256*PJ_LD] (reused: AV xw chunk [256][AV_LD], proj w chunk [256][PJ_LD],
//       out_s fp32 [64][65]), stats
#define CHUNK_ELS (CC * PJ_LD)
#define ATTN_SMEM ((NPAD*TH_LD + 64*TH_LD + 64*P_LD + 64*EMB_LD + CHUNK_ELS) * 2 + 64*2*4*2)

__global__ __launch_bounds__(256, 1) void attn_kernel(const float* __restrict__ x,
                                                      float* __restrict__ out) {
    extern __shared__ char smem_raw[];
    __nv_bfloat16* phi_sT = reinterpret_cast<__nv_bfloat16*>(smem_raw);  // [m][e] token-major
    __nv_bfloat16* th_s   = phi_sT + NPAD * TH_LD;                       // [n][e]
    __nv_bfloat16* P_s    = th_s + 64 * TH_LD;                           // [n][m]
    __nv_bfloat16* y_s    = P_s + 64 * P_LD;                             // [n][c]
    __nv_bfloat16* chunk  = y_s + 64 * EMB_LD;
    float* stats_max = reinterpret_cast<float*>(chunk + CHUNK_ELS);
    float* stats_sum = stats_max + 64 * 2;
    float* out_s = reinterpret_cast<float*>(chunk);   // reuse, fp32 [64][65]

    int w = blockIdx.x;
    int b = w / 100, rem = w % 100, wh = rem / 10, ww = rem % 10;
    int h0 = wh * WSZ, w0 = ww * WSZ;
    int tid = threadIdx.x;
    int warp = tid >> 5, lane = tid & 31;
    int rw = warp >> 1, cw = warp & 1;
    int g = lane >> 2, q = lane & 3;

    const __nv_bfloat16* embT = g_embT + (size_t)w * NPAD * CC;
    const __nv_bfloat16* xwg  = g_xw   + (size_t)w * CC * NPAD;

    // stage phi token-major: phi_sT[m][e] = embT[m][128+e]
    for (int idx = tid; idx < NPAD * CE; idx += 256) {
        int m = idx >> 7, e = idx & 127;
        phi_sT[m * TH_LD + e] = embT[m * CC + CE + e];
    }
    __syncthreads();

    const float scale = 0.08838834764831845f;  // 1/sqrt(128)

    for (int blk = 0; blk < 6; blk++) {
        // ---- stage theta rows for this block ----
        for (int idx = tid; idx < 64 * CE; idx += 256) {
            int r = idx >> 7, k = idx & 127;
            int ng = blk * 64 + r;
            th_s[r * TH_LD + k] = (ng < NPAD) ? embT[ng * CC + k] : __float2bfloat16(0.f);
        }
        __syncthreads();

        // ---- S = theta_blk @ phi^T (64x336), k=128 ----
        float sacc[21][4];
        #pragma unroll
        for (int t = 0; t < 21; t++) { sacc[t][0]=0.f; sacc[t][1]=0.f; sacc[t][2]=0.f; sacc[t][3]=0.f; }
        #pragma unroll
        for (int kt = 0; kt < 8; kt++) {
            int ar = rw * 16 + g;
            int ak = kt * 16 + q * 2;
            uint32_t a0 = lda32(&th_s[ar * TH_LD + ak]);
            uint32_t a1 = lda32(&th_s[(ar + 8) * TH_LD + ak]);
            uint32_t a2 = lda32(&th_s[ar * TH_LD + ak + 8]);
            uint32_t a3 = lda32(&th_s[(ar + 8) * TH_LD + ak + 8]);
            #pragma unroll
            for (int t = 0; t < 21; t++) {
                int ncol = cw * 168 + t * 8 + g;
                uint32_t b0 = lda32(&phi_sT[ncol * TH_LD + ak]);
                uint32_t b1 = lda32(&phi_sT[ncol * TH_LD + ak + 8]);
                mma16816(sacc[t], a0, a1, a2, a3, b0, b1);
            }
        }
        // ---- scale + column mask ----
        #pragma unroll
        for (int t = 0; t < 21; t++) {
            int c0 = cw * 168 + t * 8 + q * 2;
            #pragma unroll
            for (int i = 0; i < 4; i++) {
                float v = sacc[t][i] * scale;
                int col = c0 + (i & 1);
                if (col >= NTOK) v = -1e30f;
                sacc[t][i] = v;
            }
        }
        // ---- row max ----
        float m0 = -1e30f, m1 = -1e30f;
        #pragma unroll
        for (int t = 0; t < 21; t++) {
            m0 = fmaxf(m0, fmaxf(sacc[t][0], sacc[t][1]));
            m1 = fmaxf(m1, fmaxf(sacc[t][2], sacc[t][3]));
        }
        m0 = fmaxf(m0, __shfl_xor_sync(0xffffffffu, m0, 1));
        m0 = fmaxf(m0, __shfl_xor_sync(0xffffffffu, m0, 2));
        m1 = fmaxf(m1, __shfl_xor_sync(0xffffffffu, m1, 1));
        m1 = fmaxf(m1, __shfl_xor_sync(0xffffffffu, m1, 2));
        int row0 = rw * 16 + g, row1 = row0 + 8;
        if (q == 0) { stats_max[row0 * 2 + cw] = m0; stats_max[row1 * 2 + cw] = m1; }
        __syncthreads();
        float rmax0 = fmaxf(stats_max[row0 * 2], stats_max[row0 * 2 + 1]);
        float rmax1 = fmaxf(stats_max[row1 * 2], stats_max[row1 * 2 + 1]);
        // ---- exp + row sums ----
        float s0 = 0.f, s1 = 0.f;
        #pragma unroll
        for (int t = 0; t < 21; t++) {
            sacc[t][0] = __expf(sacc[t][0] - rmax0);
            sacc[t][1] = __expf(sacc[t][1] - rmax0);
            sacc[t][2] = __expf(sacc[t][2] - rmax1);
            sacc[t][3] = __expf(sacc[t][3] - rmax1);
            s0 += sacc[t][0] + sacc[t][1];
            s1 += sacc[t][2] + sacc[t][3];
        }
        s0 += __shfl_xor_sync(0xffffffffu, s0, 1);
        s0 += __shfl_xor_sync(0xffffffffu, s0, 2);
        s1 += __shfl_xor_sync(0xffffffffu, s1, 1);
        s1 += __shfl_xor_sync(0xffffffffu, s1, 2);
        if (q == 0) { stats_sum[row0 * 2 + cw] = s0; stats_sum[row1 * 2 + cw] = s1; }
        __syncthreads();
        float inv0 = 1.f / (stats_sum[row0 * 2] + stats_sum[row0 * 2 + 1]);
        float inv1 = 1.f / (stats_sum[row1 * 2] + stats_sum[row1 * 2 + 1]);
        // ---- write normalized P ----
        #pragma unroll
        for (int t = 0; t < 21; t++) {
            int c0 = cw * 168 + t * 8 + q * 2;
            st_bf2(&P_s[row0 * P_LD + c0], sacc[t][0] * inv0, sacc[t][1] * inv0);
            st_bf2(&P_s[row1 * P_LD + c0], sacc[t][2] * inv1, sacc[t][3] * inv1);
        }
        __syncthreads();

        // ---- y = P @ xw^T (64x256), k=336 in 7 chunks of 48; B = xw[c][m] ----
        float yacc[16][4];
        #pragma unroll
        for (int t = 0; t < 16; t++) { yacc[t][0]=0.f; yacc[t][1]=0.f; yacc[t][2]=0.f; yacc[t][3]=0.f; }
        for (int kc = 0; kc < 7; kc++) {
            for (int idx = tid; idx < CC * 48; idx += 256) {
                int c = idx / 48, mm = idx - c * 48;
                chunk[c * AV_LD + mm] = xwg[c * NPAD + kc * 48 + mm];
            }
            __syncthreads();
            #pragma unroll
            for (int kt = 0; kt < 3; kt++) {
                int ar = rw * 16 + g;
                int akg = kc * 48 + kt * 16 + q * 2;   // k in P_s
                int akl = kt * 16 + q * 2;             // k in chunk
                uint32_t a0 = lda32(&P_s[ar * P_LD + akg]);
                uint32_t a1 = lda32(&P_s[(ar + 8) * P_LD + akg]);
                uint32_t a2 = lda32(&P_s[ar * P_LD + akg + 8]);
                uint32_t a3 = lda32(&P_s[(ar + 8) * P_LD + akg + 8]);
                #pragma unroll
                for (int t = 0; t < 16; t++) {
                    int ncol = cw * 128 + t * 8 + g;
                    uint32_t b0 = lda32(&chunk[ncol * AV_LD + akl]);
                    uint32_t b1 = lda32(&chunk[ncol * AV_LD + akl + 8]);
                    mma16816(yacc[t], a0, a1, a2, a3, b0, b1);
                }
            }
            __syncthreads();
        }
        // ---- stage y (bf16) ----
        {
            int r0 = rw * 16 + g, r1 = r0 + 8;
            #pragma unroll
            for (int t = 0; t < 16; t++) {
                int c0 = cw * 128 + t * 8 + q * 2;
                st_bf2(&y_s[r0 * EMB_LD + c0], yacc[t][0], yacc[t][1]);
                st_bf2(&y_s[r1 * EMB_LD + c0], yacc[t][2], yacc[t][3]);
            }
        }
        __syncthreads();

        // ---- outp = y @ wproj^T (64x256), k=256 in 4 chunks of 64; B = wproj[o][c] ----
        float pacc[16][4];
        #pragma unroll
        for (int t = 0; t < 16; t++) { pacc[t][0]=0.f; pacc[t][1]=0.f; pacc[t][2]=0.f; pacc[t][3]=0.f; }
        for (int kc = 0; kc < 4; kc++) {
            for (int idx = tid; idx < CC * 64; idx += 256) {
                int o = idx >> 6, cc = idx & 63;
                chunk[o * PJ_LD + cc] = g_wprojb[o * CC + kc * 64 + cc];
            }
            __syncthreads();
            #pragma unroll
            for (int kt = 0; kt < 4; kt++) {
                int ar = rw * 16 + g;
                int akg = kc * 64 + kt * 16 + q * 2;   // k in y_s
                int akl = kt * 16 + q * 2;             // k in chunk
                uint32_t a0 = lda32(&y_s[ar * EMB_LD + akg]);
                uint32_t a1 = lda32(&y_s[(ar + 8) * EMB_LD + akg]);
                uint32_t a2 = lda32(&y_s[ar * EMB_LD + akg + 8]);
                uint32_t a3 = lda32(&y_s[(ar + 8) * EMB_LD + akg + 8]);
                #pragma unroll
                for (int t = 0; t < 16; t++) {
                    int ncol = cw * 128 + t * 8 + g;
                    uint32_t b0 = lda32(&chunk[ncol * PJ_LD + akl]);
                    uint32_t b1 = lda32(&chunk[ncol * PJ_LD + akl + 8]);
                    mma16816(pacc[t], a0, a1, a2, a3, b0, b1);
                }
            }
            __syncthreads();
        }

        // ---- epilogue: transpose via smem, residual add, coalesced write ----
        for (int oc = 0; oc < 4; oc++) {
            if ((oc >> 1) == cw) {
                int tb = (oc & 1) * 8;
                int r0 = rw * 16 + g, r1 = r0 + 8;
                #pragma unroll
                for (int t = 0; t < 8; t++) {
                    int cl = t * 8 + q * 2;
                    out_s[r0 * 65 + cl]     = pacc[tb + t][0];
                    out_s[r0 * 65 + cl + 1] = pacc[tb + t][1];
                    out_s[r1 * 65 + cl]     = pacc[tb + t][2];
                    out_s[r1 * 65 + cl + 1] = pacc[tb + t][3];
                }
            }
            __syncthreads();
            for (int idx = tid; idx < 64 * 64; idx += 256) {
                int ol = idx >> 6, nl = idx & 63;
                int ng = blk * 64 + nl;
                if (ng < NTOK) {
                    int o = oc * 64 + ol;
                    int i = ng / WSZ, j = ng - i * WSZ;
                    size_t gi = ((size_t)(b * CC + o) * HH + h0 + i) * HH + w0 + j;
                    out[gi] = x[gi] + out_s[nl * 65 + ol];
                }
            }
            __syncthreads();
        }
    }
}

// ---------------- launch ----------------
extern "C" void kernel_launch(void* const* d_in, const int* in_sizes, int n_in,
                              void* d_out, int out_size) {
    const float* x     = (const float*)d_in[0];
    const float* wt    = (const float*)d_in[1];
    const float* wp    = (const float*)d_in[2];
    const float* wproj = (const float*)d_in[3];
    float* out = (float*)d_out;

    cudaFuncSetAttribute(embed_kernel, cudaFuncAttributeMaxDynamicSharedMemorySize, EMBED_SMEM);
    cudaFuncSetAttribute(attn_kernel,  cudaFuncAttributeMaxDynamicSharedMemorySize, ATTN_SMEM);

    prep_kernel<<<256, 256>>>(wt, wp, wproj);
    embed_kernel<<<NWIN, 256, EMBED_SMEM>>>(x);
    attn_kernel<<<NWIN, 256, ATTN_SMEM>>>(x, out);
}

// round 6
// speedup vs baseline: 2.0374x; 1.3795x over previous
#include <cuda_runtime.h>
#include <cuda_bf16.h>
#include <cstdint>

// Problem constants
#define NWIN 400
#define NTOK 324
#define NPAD 336    // 3 * 112
#define CE   128
#define CC   256
#define HH   180
#define WSZ  18

#define BLKR  96    // token rows per block
#define NBLK  4     // 4*96 = 384 >= 336
#define SCH   112   // S/AV m-chunk
#define NTH   384   // threads

// smem leading dims (elements); (ld/2) mod 32 in {4,12,20,28} -> conflict-free
#define EMB_LD 264  // words 132, mod32=4
#define TH_LD  136  // words 68,  mod32=4
#define P_LD   344  // words 172, mod32=12
#define AV_LD  120  // words 60,  mod32=28
#define PJ_LD  136  // words 68,  mod32=4

// ---------------- global scratch ----------------
__device__ __nv_bfloat16 g_embT [NWIN * NPAD * CC];  // [w][n][e]: e<128 theta, e>=128 phi
__device__ __nv_bfloat16 g_xw   [NWIN * CC * NPAD];  // [w][c][m]
__device__ __nv_bfloat16 g_wcombb[CC * CC];          // [e][c]
__device__ __nv_bfloat16 g_wprojb[CC * CC];          // [o][c]

// ---------------- helpers ----------------
__device__ __forceinline__ uint32_t lda32(const __nv_bfloat16* p) {
    return *reinterpret_cast<const uint32_t*>(p);
}
__device__ __forceinline__ void mma16816(float* c, uint32_t a0, uint32_t a1,
                                         uint32_t a2, uint32_t a3,
                                         uint32_t b0, uint32_t b1) {
    asm volatile(
        "mma.sync.aligned.m16n8k16.row.col.f32.bf16.bf16.f32 "
        "{%0,%1,%2,%3},{%4,%5,%6,%7},{%8,%9},{%0,%1,%2,%3};\n"
        : "+f"(c[0]), "+f"(c[1]), "+f"(c[2]), "+f"(c[3])
        : "r"(a0), "r"(a1), "r"(a2), "r"(a3), "r"(b0), "r"(b1));
}
__device__ __forceinline__ void st_bf2(__nv_bfloat16* p, float lo, float hi) {
    *reinterpret_cast<__nv_bfloat162*>(p) = __floats2bfloat162_rn(lo, hi);
}
__device__ __forceinline__ void cp16(__nv_bfloat16* dst, const __nv_bfloat16* src) {
    *reinterpret_cast<uint4*>(dst) = *reinterpret_cast<const uint4*>(src);
}

// ---------------- kernel 1: weight prep ----------------
__global__ void prep_kernel(const float* __restrict__ wt, const float* __restrict__ wp,
                            const float* __restrict__ wproj) {
    int idx = blockIdx.x * blockDim.x + threadIdx.x;
    if (idx < CC * CC) {
        int r = idx >> 8, c = idx & 255;
        float v = (r < CE) ? wt[r * CC + c] : wp[(r - CE) * CC + c];
        g_wcombb[idx] = __float2bfloat16(v);
        g_wprojb[idx] = __float2bfloat16(wproj[idx]);
    }
}

// ---------------- kernel 2: window partition + embed GEMM ----------------
// smem: wcomb_s [256][EMB_LD] + xwT_blk [96][EMB_LD]
#define EMBED_SMEM ((CC * EMB_LD + BLKR * EMB_LD) * 2)

__global__ __launch_bounds__(NTH, 1) void embed_kernel(const float* __restrict__ x) {
    extern __shared__ char smem_raw[];
    __nv_bfloat16* wcomb_s = reinterpret_cast<__nv_bfloat16*>(smem_raw);   // [e][c]
    __nv_bfloat16* xwT_blk = wcomb_s + CC * EMB_LD;                        // [n][c]

    int w = blockIdx.x;
    int b = w / 100, rem = w % 100, wh = rem / 10, ww = rem % 10;
    int h0 = wh * WSZ, w0 = ww * WSZ;
    const float* xb = x + (size_t)b * CC * HH * HH;
    int tid = threadIdx.x;
    int warp = tid >> 5, lane = tid & 31;
    int rw = warp >> 1, cw = warp & 1;   // 6 row-groups x 2 col-halves
    int g = lane >> 2, q = lane & 3;

    // stage combined weight once (uint4)
    for (int idx = tid; idx < CC * 32; idx += NTH) {
        int e = idx >> 5, v = idx & 31;
        cp16(&wcomb_s[e * EMB_LD + v * 8], &g_wcombb[e * CC + v * 8]);
    }

    __nv_bfloat16* xwg  = g_xw   + (size_t)w * CC * NPAD;
    __nv_bfloat16* embT = g_embT + (size_t)w * NPAD * CC;
    __syncthreads();

    for (int blk = 0; blk < NBLK; blk++) {
        // build xwT_blk [96][256]; also emit channel-major g_xw
        for (int idx = tid; idx < BLKR * CC; idx += NTH) {
            int nn = idx % BLKR, c = idx / BLKR;
            int m = blk * BLKR + nn;
            float v = 0.f;
            if (m < NTOK) {
                int i = m / WSZ, j = m - i * WSZ;
                v = xb[((size_t)c * HH + h0 + i) * HH + w0 + j];
            }
            __nv_bfloat16 bv = __float2bfloat16(v);
            xwT_blk[nn * EMB_LD + c] = bv;
            if (m < NPAD) xwg[c * NPAD + m] = bv;
        }
        __syncthreads();

        // embT_blk = xwT_blk @ wcomb^T : [96][256], k=256
        float acc[16][4];
        #pragma unroll
        for (int t = 0; t < 16; t++) { acc[t][0]=0.f; acc[t][1]=0.f; acc[t][2]=0.f; acc[t][3]=0.f; }
        #pragma unroll
        for (int kt = 0; kt < 16; kt++) {
            int ar = rw * 16 + g;
            int ak = kt * 16 + q * 2;
            uint32_t a0 = lda32(&xwT_blk[ar * EMB_LD + ak]);
            uint32_t a1 = lda32(&xwT_blk[(ar + 8) * EMB_LD + ak]);
            uint32_t a2 = lda32(&xwT_blk[ar * EMB_LD + ak + 8]);
            uint32_t a3 = lda32(&xwT_blk[(ar + 8) * EMB_LD + ak + 8]);
            #pragma unroll
            for (int t = 0; t < 16; t++) {
                int ncol = cw * 128 + t * 8 + g;
                uint32_t b0 = lda32(&wcomb_s[ncol * EMB_LD + ak]);
                uint32_t b1 = lda32(&wcomb_s[ncol * EMB_LD + ak + 8]);
                mma16816(acc[t], a0, a1, a2, a3, b0, b1);
            }
        }
        {
            int r0 = blk * BLKR + rw * 16 + g, r1 = r0 + 8;
            #pragma unroll
            for (int t = 0; t < 16; t++) {
                int e0 = cw * 128 + t * 8 + q * 2;
                if (r0 < NPAD) st_bf2(&embT[r0 * CC + e0], acc[t][0], acc[t][1]);
                if (r1 < NPAD) st_bf2(&embT[r1 * CC + e0], acc[t][2], acc[t][3]);
            }
        }
        __syncthreads();
    }
}

// ---------------- kernel 3: fused attention + projection + residual ----------------
// smem: th_s [96][TH_LD], P_s [96][P_LD], y_s [96][EMB_LD], chunk [256*PJ_LD]
//       (chunk reused: phi chunks [112][TH_LD], AV xw chunks [256][AV_LD],
//        proj w chunks [256][PJ_LD], out_s fp32 [96][65]), stats
#define CHUNK_ELS (CC * PJ_LD)
#define ATTN_SMEM ((BLKR*TH_LD + BLKR*P_LD + BLKR*EMB_LD + CHUNK_ELS) * 2 + BLKR*2*4*2)

__global__ __launch_bounds__(NTH, 1) void attn_kernel(const float* __restrict__ x,
                                                      float* __restrict__ out) {
    extern __shared__ char smem_raw[];
    __nv_bfloat16* th_s  = reinterpret_cast<__nv_bfloat16*>(smem_raw);   // [n][e]
    __nv_bfloat16* P_s   = th_s + BLKR * TH_LD;                          // [n][m]
    __nv_bfloat16* y_s   = P_s + BLKR * P_LD;                            // [n][c]
    __nv_bfloat16* chunk = y_s + BLKR * EMB_LD;
    float* stats_max = reinterpret_cast<float*>(chunk + CHUNK_ELS);
    float* stats_sum = stats_max + BLKR * 2;
    float* out_s = reinterpret_cast<float*>(chunk);                      // fp32 [96][65]

    int w = blockIdx.x;
    int b = w / 100, rem = w % 100, wh = rem / 10, ww = rem % 10;
    int h0 = wh * WSZ, w0 = ww * WSZ;
    int tid = threadIdx.x;
    int warp = tid >> 5, lane = tid & 31;
    int rw = warp >> 1, cw = warp & 1;   // 6 x 2
    int g = lane >> 2, q = lane & 3;

    const __nv_bfloat16* embT = g_embT + (size_t)w * NPAD * CC;
    const __nv_bfloat16* xwg  = g_xw   + (size_t)w * CC * NPAD;

    const float scale = 0.08838834764831845f;  // 1/sqrt(128)

    for (int blk = 0; blk < NBLK; blk++) {
        // ---- stage theta rows (uint4) ----
        for (int idx = tid; idx < BLKR * 16; idx += NTH) {
            int r = idx >> 4, v = idx & 15;
            int ng = blk * BLKR + r;
            if (ng < NPAD) cp16(&th_s[r * TH_LD + v * 8], &embT[ng * CC + v * 8]);
            else *reinterpret_cast<uint4*>(&th_s[r * TH_LD + v * 8]) = make_uint4(0,0,0,0);
        }
        __syncthreads();

        // ---- S = theta_blk @ phi^T (96x336), k=128, phi streamed in 3x112 ----
        float sacc[21][4];
        #pragma unroll
        for (int t = 0; t < 21; t++) { sacc[t][0]=0.f; sacc[t][1]=0.f; sacc[t][2]=0.f; sacc[t][3]=0.f; }
        for (int mc = 0; mc < 3; mc++) {
            // stage phi chunk [112][128] token-major (cols 128..255 of embT)
            for (int idx = tid; idx < SCH * 16; idx += NTH) {
                int mm = idx >> 4, v = idx & 15;
                cp16(&chunk[mm * TH_LD + v * 8], &embT[(mc * SCH + mm) * CC + CE + v * 8]);
            }
            __syncthreads();
            #pragma unroll
            for (int kt = 0; kt < 8; kt++) {
                int ar = rw * 16 + g;
                int ak = kt * 16 + q * 2;
                uint32_t a0 = lda32(&th_s[ar * TH_LD + ak]);
                uint32_t a1 = lda32(&th_s[(ar + 8) * TH_LD + ak]);
                uint32_t a2 = lda32(&th_s[ar * TH_LD + ak + 8]);
                uint32_t a3 = lda32(&th_s[(ar + 8) * TH_LD + ak + 8]);
                #pragma unroll
                for (int t = 0; t < 7; t++) {
                    int ncol = cw * 56 + t * 8 + g;   // local col in chunk
                    uint32_t b0 = lda32(&chunk[ncol * TH_LD + ak]);
                    uint32_t b1 = lda32(&chunk[ncol * TH_LD + ak + 8]);
                    mma16816(sacc[mc * 7 + t], a0, a1, a2, a3, b0, b1);
                }
            }
            __syncthreads();
        }
        // ---- scale + column mask ----
        #pragma unroll
        for (int mc = 0; mc < 3; mc++) {
            #pragma unroll
            for (int t = 0; t < 7; t++) {
                int c0 = mc * SCH + cw * 56 + t * 8 + q * 2;
                float* sv = sacc[mc * 7 + t];
                #pragma unroll
                for (int i = 0; i < 4; i++) {
                    float v = sv[i] * scale;
                    int col = c0 + (i & 1);
                    if (col >= NTOK) v = -1e30f;
                    sv[i] = v;
                }
            }
        }
        // ---- row max ----
        float m0 = -1e30f, m1 = -1e30f;
        #pragma unroll
        for (int t = 0; t < 21; t++) {
            m0 = fmaxf(m0, fmaxf(sacc[t][0], sacc[t][1]));
            m1 = fmaxf(m1, fmaxf(sacc[t][2], sacc[t][3]));
        }
        m0 = fmaxf(m0, __shfl_xor_sync(0xffffffffu, m0, 1));
        m0 = fmaxf(m0, __shfl_xor_sync(0xffffffffu, m0, 2));
        m1 = fmaxf(m1, __shfl_xor_sync(0xffffffffu, m1, 1));
        m1 = fmaxf(m1, __shfl_xor_sync(0xffffffffu, m1, 2));
        int row0 = rw * 16 + g, row1 = row0 + 8;
        if (q == 0) { stats_max[row0 * 2 + cw] = m0; stats_max[row1 * 2 + cw] = m1; }
        __syncthreads();
        float rmax0 = fmaxf(stats_max[row0 * 2], stats_max[row0 * 2 + 1]);
        float rmax1 = fmaxf(stats_max[row1 * 2], stats_max[row1 * 2 + 1]);
        // ---- exp + row sums ----
        float s0 = 0.f, s1 = 0.f;
        #pragma unroll
        for (int t = 0; t < 21; t++) {
            sacc[t][0] = __expf(sacc[t][0] - rmax0);
            sacc[t][1] = __expf(sacc[t][1] - rmax0);
            sacc[t][2] = __expf(sacc[t][2] - rmax1);
            sacc[t][3] = __expf(sacc[t][3] - rmax1);
            s0 += sacc[t][0] + sacc[t][1];
            s1 += sacc[t][2] + sacc[t][3];
        }
        s0 += __shfl_xor_sync(0xffffffffu, s0, 1);
        s0 += __shfl_xor_sync(0xffffffffu, s0, 2);
        s1 += __shfl_xor_sync(0xffffffffu, s1, 1);
        s1 += __shfl_xor_sync(0xffffffffu, s1, 2);
        if (q == 0) { stats_sum[row0 * 2 + cw] = s0; stats_sum[row1 * 2 + cw] = s1; }
        __syncthreads();
        float inv0 = 1.f / (stats_sum[row0 * 2] + stats_sum[row0 * 2 + 1]);
        float inv1 = 1.f / (stats_sum[row1 * 2] + stats_sum[row1 * 2 + 1]);
        // ---- write normalized P ----
        #pragma unroll
        for (int mc = 0; mc < 3; mc++) {
            #pragma unroll
            for (int t = 0; t < 7; t++) {
                int c0 = mc * SCH + cw * 56 + t * 8 + q * 2;
                float* sv = sacc[mc * 7 + t];
                st_bf2(&P_s[row0 * P_LD + c0], sv[0] * inv0, sv[1] * inv0);
                st_bf2(&P_s[row1 * P_LD + c0], sv[2] * inv1, sv[3] * inv1);
            }
        }
        __syncthreads();

        // ---- y = P @ xw^T (96x256), k=336 in 3 chunks of 112; B = xw[c][m] ----
        float yacc[16][4];
        #pragma unroll
        for (int t = 0; t < 16; t++) { yacc[t][0]=0.f; yacc[t][1]=0.f; yacc[t][2]=0.f; yacc[t][3]=0.f; }
        for (int mc = 0; mc < 3; mc++) {
            for (int idx = tid; idx < CC * 14; idx += NTH) {
                int c = idx / 14, v = idx % 14;
                cp16(&chunk[c * AV_LD + v * 8], &xwg[c * NPAD + mc * SCH + v * 8]);
            }
            __syncthreads();
            #pragma unroll
            for (int kt = 0; kt < 7; kt++) {
                int ar = rw * 16 + g;
                int akg = mc * SCH + kt * 16 + q * 2;
                int akl = kt * 16 + q * 2;
                uint32_t a0 = lda32(&P_s[ar * P_LD + akg]);
                uint32_t a1 = lda32(&P_s[(ar + 8) * P_LD + akg]);
                uint32_t a2 = lda32(&P_s[ar * P_LD + akg + 8]);
                uint32_t a3 = lda32(&P_s[(ar + 8) * P_LD + akg + 8]);
                #pragma unroll
                for (int t = 0; t < 16; t++) {
                    int ncol = cw * 128 + t * 8 + g;
                    uint32_t b0 = lda32(&chunk[ncol * AV_LD + akl]);
                    uint32_t b1 = lda32(&chunk[ncol * AV_LD + akl + 8]);
                    mma16816(yacc[t], a0, a1, a2, a3, b0, b1);
                }
            }
            __syncthreads();
        }
        // ---- stage y (bf16) ----
        {
            int r0 = rw * 16 + g, r1 = r0 + 8;
            #pragma unroll
            for (int t = 0; t < 16; t++) {
                int c0 = cw * 128 + t * 8 + q * 2;
                st_bf2(&y_s[r0 * EMB_LD + c0], yacc[t][0], yacc[t][1]);
                st_bf2(&y_s[r1 * EMB_LD + c0], yacc[t][2], yacc[t][3]);
            }
        }
        __syncthreads();

        // ---- outp = y @ wproj^T (96x256), k=256 in 2 chunks of 128 ----
        float pacc[16][4];
        #pragma unroll
        for (int t = 0; t < 16; t++) { pacc[t][0]=0.f; pacc[t][1]=0.f; pacc[t][2]=0.f; pacc[t][3]=0.f; }
        for (int kc = 0; kc < 2; kc++) {
            for (int idx = tid; idx < CC * 16; idx += NTH) {
                int o = idx >> 4, v = idx & 15;
                cp16(&chunk[o * PJ_LD + v * 8], &g_wprojb[o * CC + kc * 128 + v * 8]);
            }
            __syncthreads();
            #pragma unroll
            for (int kt = 0; kt < 8; kt++) {
                int ar = rw * 16 + g;
                int akg = kc * 128 + kt * 16 + q * 2;
                int akl = kt * 16 + q * 2;
                uint32_t a0 = lda32(&y_s[ar * EMB_LD + akg]);
                uint32_t a1 = lda32(&y_s[(ar + 8) * EMB_LD + akg]);
                uint32_t a2 = lda32(&y_s[ar * EMB_LD + akg + 8]);
                uint32_t a3 = lda32(&y_s[(ar + 8) * EMB_LD + akg + 8]);
                #pragma unroll
                for (int t = 0; t < 16; t++) {
                    int ncol = cw * 128 + t * 8 + g;
                    uint32_t b0 = lda32(&chunk[ncol * PJ_LD + akl]);
                    uint32_t b1 = lda32(&chunk[ncol * PJ_LD + akl + 8]);
                    mma16816(pacc[t], a0, a1, a2, a3, b0, b1);
                }
            }
            __syncthreads();
        }

        // ---- epilogue: transpose via smem, residual add, coalesced write ----
        for (int oc = 0; oc < 4; oc++) {     // 4 chunks of 64 channels
            if ((oc >> 1) == cw) {
                int tb = (oc & 1) * 8;
                int r0 = rw * 16 + g, r1 = r0 + 8;
                #pragma unroll
                for (int t = 0; t < 8; t++) {
                    int cl = t * 8 + q * 2;
                    out_s[r0 * 65 + cl]     = pacc[tb + t][0];
                    out_s[r0 * 65 + cl + 1] = pacc[tb + t][1];
                    out_s[r1 * 65 + cl]     = pacc[tb + t][2];
                    out_s[r1 * 65 + cl + 1] = pacc[tb + t][3];
                }
            }
            __syncthreads();
            for (int idx = tid; idx < BLKR * 64; idx += NTH) {
                int nl = idx % BLKR, ol = idx / BLKR;
                int ng = blk * BLKR + nl;
                if (ng < NTOK) {
                    int o = oc * 64 + ol;
                    int i = ng / WSZ, j = ng - i * WSZ;
                    size_t gi = ((size_t)(b * CC + o) * HH + h0 + i) * HH + w0 + j;
                    out[gi] = x[gi] + out_s[nl * 65 + ol];
                }
            }
            __syncthreads();
        }
    }
}

// ---------------- launch ----------------
extern "C" void kernel_launch(void* const* d_in, const int* in_sizes, int n_in,
                              void* d_out, int out_size) {
    const float* x     = (const float*)d_in[0];
    const float* wt    = (const float*)d_in[1];
    const float* wp    = (const float*)d_in[2];
    const float* wproj = (const float*)d_in[3];
    float* out = (float*)d_out;

    cudaFuncSetAttribute(embed_kernel, cudaFuncAttributeMaxDynamicSharedMemorySize, EMBED_SMEM);
    cudaFuncSetAttribute(attn_kernel,  cudaFuncAttributeMaxDynamicSharedMemorySize, ATTN_SMEM);

    prep_kernel<<<256, 256>>>(wt, wp, wproj);
    embed_kernel<<<NWIN, NTH, EMBED_SMEM>>>(x);
    attn_kernel<<<NWIN, NTH, ATTN_SMEM>>>(x, out);
}

// round 8
// speedup vs baseline: 2.0794x; 1.0206x over previous
#include <cuda_runtime.h>
#include <cuda_bf16.h>
#include <cstdint>

// Problem constants
#define NWIN 400
#define NTOK 324
#define NPAD 336    // 3 * 112, 7 * 48
#define CE   128
#define CC   256
#define HH   180
#define WSZ  18

#define BLKR  96    // token rows per block
#define NBLK  4
#define SCH   112   // S phi m-chunk
#define AVK   48    // AV k-chunk
#define NTH   384   // threads

// smem leading dims (elements); (ld/2) mod 32 in {4,12,20,28} -> conflict-free
#define EMB_LD 264  // words 132, mod32=4
#define TH_LD  136  // words 68,  mod32=4
#define P_LD   344  // words 172, mod32=12
#define AV_LD  56   // words 28,  mod32=28
#define PJ_LD  136  // words 68,  mod32=4

// per-half ping-pong buffer; 2*CHUNK_HALF must also hold the proj staging
// footprint [256][PJ_LD] = 34816 elems (the R7 bug: it was sized 15232 and
// proj staging overran smem). 2*17408 = 34816 exactly; each half >= phi chunk
// (112*TH_LD = 15232) and AV chunk (256*AV_LD = 14336).
#define CHUNK_HALF 17408

// ---------------- global scratch ----------------
__device__ __nv_bfloat16 g_embT [NWIN * NPAD * CC];  // [w][n][e]: e<128 theta, e>=128 phi
__device__ __nv_bfloat16 g_xw   [NWIN * CC * NPAD];  // [w][c][m]
__device__ __nv_bfloat16 g_wprojb[CC * CC];          // [o][c] (written by embed block 0)

// ---------------- helpers ----------------
__device__ __forceinline__ uint32_t lda32(const __nv_bfloat16* p) {
    return *reinterpret_cast<const uint32_t*>(p);
}
__device__ __forceinline__ void mma16816(float* c, uint32_t a0, uint32_t a1,
                                         uint32_t a2, uint32_t a3,
                                         uint32_t b0, uint32_t b1) {
    asm volatile(
        "mma.sync.aligned.m16n8k16.row.col.f32.bf16.bf16.f32 "
        "{%0,%1,%2,%3},{%4,%5,%6,%7},{%8,%9},{%0,%1,%2,%3};\n"
        : "+f"(c[0]), "+f"(c[1]), "+f"(c[2]), "+f"(c[3])
        : "r"(a0), "r"(a1), "r"(a2), "r"(a3), "r"(b0), "r"(b1));
}
__device__ __forceinline__ void st_bf2(__nv_bfloat16* p, float lo, float hi) {
    *reinterpret_cast<__nv_bfloat162*>(p) = __floats2bfloat162_rn(lo, hi);
}
__device__ __forceinline__ void cp16(__nv_bfloat16* dst, const __nv_bfloat16* src) {
    *reinterpret_cast<uint4*>(dst) = *reinterpret_cast<const uint4*>(src);
}
__device__ __forceinline__ void cpasync16(__nv_bfloat16* smem_dst, const __nv_bfloat16* gsrc) {
    uint32_t s = (uint32_t)__cvta_generic_to_shared(smem_dst);
    asm volatile("cp.async.cg.shared.global [%0], [%1], 16;\n" :: "r"(s), "l"(gsrc));
}
#define CP_COMMIT() asm volatile("cp.async.commit_group;\n" ::: "memory")
#define CP_WAIT1()  asm volatile("cp.async.wait_group 1;\n" ::: "memory")
#define CP_WAIT0()  asm volatile("cp.async.wait_group 0;\n" ::: "memory")

// ---------------- kernel 1: window partition + embed GEMM (also preps wproj) ----
// smem: wcomb_s [256][EMB_LD] + xwT_blk [96][EMB_LD]
#define EMBED_SMEM ((CC * EMB_LD + BLKR * EMB_LD) * 2)

__global__ __launch_bounds__(NTH, 1) void embed_kernel(const float* __restrict__ x,
                                                       const float* __restrict__ wt,
                                                       const float* __restrict__ wp,
                                                       const float* __restrict__ wproj) {
    extern __shared__ char smem_raw[];
    __nv_bfloat16* wcomb_s = reinterpret_cast<__nv_bfloat16*>(smem_raw);   // [e][c]
    __nv_bfloat16* xwT_blk = wcomb_s + CC * EMB_LD;                        // [n][c]

    int w = blockIdx.x;
    int b = w / 100, rem = w % 100, wh = rem / 10, ww = rem % 10;
    int h0 = wh * WSZ, w0 = ww * WSZ;
    const float* xb = x + (size_t)b * CC * HH * HH;
    int tid = threadIdx.x;
    int warp = tid >> 5, lane = tid & 31;
    int rw = warp >> 1, cw = warp & 1;   // 6 row-groups x 2 col-halves
    int g = lane >> 2, q = lane & 3;

    // block 0 additionally converts wproj -> g_wprojb (bf16) for the attn kernel
    if (blockIdx.x == 0) {
        for (int idx = tid; idx < CC * CC / 4; idx += NTH) {
            float4 f = *reinterpret_cast<const float4*>(&wproj[idx * 4]);
            __nv_bfloat162 lo = __floats2bfloat162_rn(f.x, f.y);
            __nv_bfloat162 hi = __floats2bfloat162_rn(f.z, f.w);
            uint2 v; v.x = *reinterpret_cast<uint32_t*>(&lo); v.y = *reinterpret_cast<uint32_t*>(&hi);
            *reinterpret_cast<uint2*>(&g_wprojb[idx * 4]) = v;
        }
    }

    // stage combined weight (convert float -> bf16), float4 loads
    for (int idx = tid; idx < CC * 64; idx += NTH) {
        int e = idx >> 6, v = idx & 63;
        const float* src = (e < CE) ? &wt[e * CC + v * 4] : &wp[(e - CE) * CC + v * 4];
        float4 f = *reinterpret_cast<const float4*>(src);
        __nv_bfloat162 lo = __floats2bfloat162_rn(f.x, f.y);
        __nv_bfloat162 hi = __floats2bfloat162_rn(f.z, f.w);
        uint2 o; o.x = *reinterpret_cast<uint32_t*>(&lo); o.y = *reinterpret_cast<uint32_t*>(&hi);
        *reinterpret_cast<uint2*>(&wcomb_s[e * EMB_LD + v * 4]) = o;
    }

    __nv_bfloat16* xwg  = g_xw   + (size_t)w * CC * NPAD;
    __nv_bfloat16* embT = g_embT + (size_t)w * NPAD * CC;
    __syncthreads();

    for (int blk = 0; blk < NBLK; blk++) {
        for (int idx = tid; idx < BLKR * CC; idx += NTH) {
            int nn = idx % BLKR, c = idx / BLKR;
            int m = blk * BLKR + nn;
            float v = 0.f;
            if (m < NTOK) {
                int i = m / WSZ, j = m - i * WSZ;
                v = xb[((size_t)c * HH + h0 + i) * HH + w0 + j];
            }
            __nv_bfloat16 bv = __float2bfloat16(v);
            xwT_blk[nn * EMB_LD + c] = bv;
            if (m < NPAD) xwg[c * NPAD + m] = bv;
        }
        __syncthreads();

        float acc[16][4];
        #pragma unroll
        for (int t = 0; t < 16; t++) { acc[t][0]=0.f; acc[t][1]=0.f; acc[t][2]=0.f; acc[t][3]=0.f; }
        #pragma unroll
        for (int kt = 0; kt < 16; kt++) {
            int ar = rw * 16 + g;
            int ak = kt * 16 + q * 2;
            uint32_t a0 = lda32(&xwT_blk[ar * EMB_LD + ak]);
            uint32_t a1 = lda32(&xwT_blk[(ar + 8) * EMB_LD + ak]);
            uint32_t a2 = lda32(&xwT_blk[ar * EMB_LD + ak + 8]);
            uint32_t a3 = lda32(&xwT_blk[(ar + 8) * EMB_LD + ak + 8]);
            #pragma unroll
            for (int t = 0; t < 16; t++) {
                int ncol = cw * 128 + t * 8 + g;
                uint32_t b0 = lda32(&wcomb_s[ncol * EMB_LD + ak]);
                uint32_t b1 = lda32(&wcomb_s[ncol * EMB_LD + ak + 8]);
                mma16816(acc[t], a0, a1, a2, a3, b0, b1);
            }
        }
        {
            int r0 = blk * BLKR + rw * 16 + g, r1 = r0 + 8;
            #pragma unroll
            for (int t = 0; t < 16; t++) {
                int e0 = cw * 128 + t * 8 + q * 2;
                if (r0 < NPAD) st_bf2(&embT[r0 * CC + e0], acc[t][0], acc[t][1]);
                if (r1 < NPAD) st_bf2(&embT[r1 * CC + e0], acc[t][2], acc[t][3]);
            }
        }
        __syncthreads();
    }
}

// ---------------- kernel 2: fused attention + projection + residual ----------------
#define ATTN_SMEM ((BLKR*TH_LD + BLKR*P_LD + BLKR*EMB_LD + 2*CHUNK_HALF) * 2 + BLKR*2*4*2)

__global__ __launch_bounds__(NTH, 1) void attn_kernel(const float* __restrict__ x,
                                                      float* __restrict__ out) {
    extern __shared__ char smem_raw[];
    __nv_bfloat16* th_s  = reinterpret_cast<__nv_bfloat16*>(smem_raw);   // [n][e]
    __nv_bfloat16* P_s   = th_s + BLKR * TH_LD;                          // [n][m]
    __nv_bfloat16* y_s   = P_s + BLKR * P_LD;                            // [n][c]
    __nv_bfloat16* chunk = y_s + BLKR * EMB_LD;                          // 2 x CHUNK_HALF
    float* stats_max = reinterpret_cast<float*>(chunk + 2 * CHUNK_HALF);
    float* stats_sum = stats_max + BLKR * 2;
    float* out_s = reinterpret_cast<float*>(chunk);                      // fp32 [96][65]

    __nv_bfloat16* buf[2] = {chunk, chunk + CHUNK_HALF};

    int w = blockIdx.x;
    int b = w / 100, rem = w % 100, wh = rem / 10, ww = rem % 10;
    int h0 = wh * WSZ, w0 = ww * WSZ;
    int tid = threadIdx.x;
    int warp = tid >> 5, lane = tid & 31;
    int rw = warp >> 1, cw = warp & 1;   // 6 x 2
    int g = lane >> 2, q = lane & 3;

    const __nv_bfloat16* embT = g_embT + (size_t)w * NPAD * CC;
    const __nv_bfloat16* xwg  = g_xw   + (size_t)w * CC * NPAD;

    const float scale = 0.08838834764831845f;  // 1/sqrt(128)

    for (int blk = 0; blk < NBLK; blk++) {
        // ---- prefetch phi chunk 0 (async), then stage theta rows ----
        for (int idx = tid; idx < SCH * 16; idx += NTH) {
            int mm = idx >> 4, v = idx & 15;
            cpasync16(&buf[0][mm * TH_LD + v * 8], &embT[mm * CC + CE + v * 8]);
        }
        CP_COMMIT();
        for (int idx = tid; idx < BLKR * 16; idx += NTH) {
            int r = idx >> 4, v = idx & 15;
            int ng = blk * BLKR + r;
            if (ng < NPAD) cp16(&th_s[r * TH_LD + v * 8], &embT[ng * CC + v * 8]);
            else *reinterpret_cast<uint4*>(&th_s[r * TH_LD + v * 8]) = make_uint4(0,0,0,0);
        }

        // ---- S = theta_blk @ phi^T (96x336), k=128, 3 double-buffered chunks ----
        float sacc[21][4];
        #pragma unroll
        for (int t = 0; t < 21; t++) { sacc[t][0]=0.f; sacc[t][1]=0.f; sacc[t][2]=0.f; sacc[t][3]=0.f; }
        for (int mc = 0; mc < 3; mc++) {
            if (mc < 2) {
                for (int idx = tid; idx < SCH * 16; idx += NTH) {
                    int mm = idx >> 4, v = idx & 15;
                    cpasync16(&buf[(mc + 1) & 1][mm * TH_LD + v * 8],
                              &embT[((mc + 1) * SCH + mm) * CC + CE + v * 8]);
                }
                CP_COMMIT();
                CP_WAIT1();
            } else {
                CP_WAIT0();
            }
            __syncthreads();
            const __nv_bfloat16* pc = buf[mc & 1];
            #pragma unroll
            for (int kt = 0; kt < 8; kt++) {
                int ar = rw * 16 + g;
                int ak = kt * 16 + q * 2;
                uint32_t a0 = lda32(&th_s[ar * TH_LD + ak]);
                uint32_t a1 = lda32(&th_s[(ar + 8) * TH_LD + ak]);
                uint32_t a2 = lda32(&th_s[ar * TH_LD + ak + 8]);
                uint32_t a3 = lda32(&th_s[(ar + 8) * TH_LD + ak + 8]);
                #pragma unroll
                for (int t = 0; t < 7; t++) {
                    int ncol = cw * 56 + t * 8 + g;
                    uint32_t b0 = lda32(&pc[ncol * TH_LD + ak]);
                    uint32_t b1 = lda32(&pc[ncol * TH_LD + ak + 8]);
                    mma16816(sacc[mc * 7 + t], a0, a1, a2, a3, b0, b1);
                }
            }
            __syncthreads();
        }
        // ---- scale + column mask ----
        #pragma unroll
        for (int mc = 0; mc < 3; mc++) {
            #pragma unroll
            for (int t = 0; t < 7; t++) {
                int c0 = mc * SCH + cw * 56 + t * 8 + q * 2;
                float* sv = sacc[mc * 7 + t];
                #pragma unroll
                for (int i = 0; i < 4; i++) {
                    float v = sv[i] * scale;
                    int col = c0 + (i & 1);
                    if (col >= NTOK) v = -1e30f;
                    sv[i] = v;
                }
            }
        }
        // ---- row max ----
        float m0 = -1e30f, m1 = -1e30f;
        #pragma unroll
        for (int t = 0; t < 21; t++) {
            m0 = fmaxf(m0, fmaxf(sacc[t][0], sacc[t][1]));
            m1 = fmaxf(m1, fmaxf(sacc[t][2], sacc[t][3]));
        }
        m0 = fmaxf(m0, __shfl_xor_sync(0xffffffffu, m0, 1));
        m0 = fmaxf(m0, __shfl_xor_sync(0xffffffffu, m0, 2));
        m1 = fmaxf(m1, __shfl_xor_sync(0xffffffffu, m1, 1));
        m1 = fmaxf(m1, __shfl_xor_sync(0xffffffffu, m1, 2));
        int row0 = rw * 16 + g, row1 = row0 + 8;
        if (q == 0) { stats_max[row0 * 2 + cw] = m0; stats_max[row1 * 2 + cw] = m1; }
        __syncthreads();
        float rmax0 = fmaxf(stats_max[row0 * 2], stats_max[row0 * 2 + 1]);
        float rmax1 = fmaxf(stats_max[row1 * 2], stats_max[row1 * 2 + 1]);
        // ---- exp + row sums ----
        float s0 = 0.f, s1 = 0.f;
        #pragma unroll
        for (int t = 0; t < 21; t++) {
            sacc[t][0] = __expf(sacc[t][0] - rmax0);
            sacc[t][1] = __expf(sacc[t][1] - rmax0);
            sacc[t][2] = __expf(sacc[t][2] - rmax1);
            sacc[t][3] = __expf(sacc[t][3] - rmax1);
            s0 += sacc[t][0] + sacc[t][1];
            s1 += sacc[t][2] + sacc[t][3];
        }
        s0 += __shfl_xor_sync(0xffffffffu, s0, 1);
        s0 += __shfl_xor_sync(0xffffffffu, s0, 2);
        s1 += __shfl_xor_sync(0xffffffffu, s1, 1);
        s1 += __shfl_xor_sync(0xffffffffu, s1, 2);
        if (q == 0) { stats_sum[row0 * 2 + cw] = s0; stats_sum[row1 * 2 + cw] = s1; }
        __syncthreads();
        float inv0 = 1.f / (stats_sum[row0 * 2] + stats_sum[row0 * 2 + 1]);
        float inv1 = 1.f / (stats_sum[row1 * 2] + stats_sum[row1 * 2 + 1]);
        // ---- write normalized P ----
        #pragma unroll
        for (int mc = 0; mc < 3; mc++) {
            #pragma unroll
            for (int t = 0; t < 7; t++) {
                int c0 = mc * SCH + cw * 56 + t * 8 + q * 2;
                float* sv = sacc[mc * 7 + t];
                st_bf2(&P_s[row0 * P_LD + c0], sv[0] * inv0, sv[1] * inv0);
                st_bf2(&P_s[row1 * P_LD + c0], sv[2] * inv1, sv[3] * inv1);
            }
        }
        // prefetch AV chunk 0 (async); the loop's first barrier publishes P_s too
        for (int idx = tid; idx < CC * (AVK / 8); idx += NTH) {
            int c = idx / (AVK / 8), v = idx % (AVK / 8);
            cpasync16(&buf[0][c * AV_LD + v * 8], &xwg[c * NPAD + v * 8]);
        }
        CP_COMMIT();

        // ---- y = P @ xw^T (96x256), k=336 in 7 double-buffered chunks of 48 ----
        float yacc[16][4];
        #pragma unroll
        for (int t = 0; t < 16; t++) { yacc[t][0]=0.f; yacc[t][1]=0.f; yacc[t][2]=0.f; yacc[t][3]=0.f; }
        for (int mc = 0; mc < 7; mc++) {
            if (mc < 6) {
                for (int idx = tid; idx < CC * (AVK / 8); idx += NTH) {
                    int c = idx / (AVK / 8), v = idx % (AVK / 8);
                    cpasync16(&buf[(mc + 1) & 1][c * AV_LD + v * 8],
                              &xwg[c * NPAD + (mc + 1) * AVK + v * 8]);
                }
                CP_COMMIT();
                CP_WAIT1();
            } else {
                CP_WAIT0();
            }
            __syncthreads();
            const __nv_bfloat16* av = buf[mc & 1];
            #pragma unroll
            for (int kt = 0; kt < 3; kt++) {
                int ar = rw * 16 + g;
                int akg = mc * AVK + kt * 16 + q * 2;
                int akl = kt * 16 + q * 2;
                uint32_t a0 = lda32(&P_s[ar * P_LD + akg]);
                uint32_t a1 = lda32(&P_s[(ar + 8) * P_LD + akg]);
                uint32_t a2 = lda32(&P_s[ar * P_LD + akg + 8]);
                uint32_t a3 = lda32(&P_s[(ar + 8) * P_LD + akg + 8]);
                #pragma unroll
                for (int t = 0; t < 16; t++) {
                    int ncol = cw * 128 + t * 8 + g;
                    uint32_t b0 = lda32(&av[ncol * AV_LD + akl]);
                    uint32_t b1 = lda32(&av[ncol * AV_LD + akl + 8]);
                    mma16816(yacc[t], a0, a1, a2, a3, b0, b1);
                }
            }
            __syncthreads();
        }
        // ---- stage y (bf16) ----
        {
            int r0 = rw * 16 + g, r1 = r0 + 8;
            #pragma unroll
            for (int t = 0; t < 16; t++) {
                int c0 = cw * 128 + t * 8 + q * 2;
                st_bf2(&y_s[r0 * EMB_LD + c0], yacc[t][0], yacc[t][1]);
                st_bf2(&y_s[r1 * EMB_LD + c0], yacc[t][2], yacc[t][3]);
            }
        }
        __syncthreads();

        // ---- outp = y @ wproj^T (96x256), k=256 in 2 chunks of 128 ----
        float pacc[16][4];
        #pragma unroll
        for (int t = 0; t < 16; t++) { pacc[t][0]=0.f; pacc[t][1]=0.f; pacc[t][2]=0.f; pacc[t][3]=0.f; }
        for (int kc = 0; kc < 2; kc++) {
            for (int idx = tid; idx < CC * 16; idx += NTH) {
                int o = idx >> 4, v = idx & 15;
                cp16(&chunk[o * PJ_LD + v * 8], &g_wprojb[o * CC + kc * 128 + v * 8]);
            }
            __syncthreads();
            #pragma unroll
            for (int kt = 0; kt < 8; kt++) {
                int ar = rw * 16 + g;
                int akg = kc * 128 + kt * 16 + q * 2;
                int akl = kt * 16 + q * 2;
                uint32_t a0 = lda32(&y_s[ar * EMB_LD + akg]);
                uint32_t a1 = lda32(&y_s[(ar + 8) * EMB_LD + akg]);
                uint32_t a2 = lda32(&y_s[ar * EMB_LD + akg + 8]);
                uint32_t a3 = lda32(&y_s[(ar + 8) * EMB_LD + akg + 8]);
                #pragma unroll
                for (int t = 0; t < 16; t++) {
                    int ncol = cw * 128 + t * 8 + g;
                    uint32_t b0 = lda32(&chunk[ncol * PJ_LD + akl]);
                    uint32_t b1 = lda32(&chunk[ncol * PJ_LD + akl + 8]);
                    mma16816(pacc[t], a0, a1, a2, a3, b0, b1);
                }
            }
            __syncthreads();
        }

        // ---- epilogue: transpose via smem, residual add, coalesced write ----
        for (int oc = 0; oc < 4; oc++) {
            if ((oc >> 1) == cw) {
                int tb = (oc & 1) * 8;
                int r0 = rw * 16 + g, r1 = r0 + 8;
                #pragma unroll
                for (int t = 0; t < 8; t++) {
                    int cl = t * 8 + q * 2;
                    out_s[r0 * 65 + cl]     = pacc[tb + t][0];
                    out_s[r0 * 65 + cl + 1] = pacc[tb + t][1];
                    out_s[r1 * 65 + cl]     = pacc[tb + t][2];
                    out_s[r1 * 65 + cl + 1] = pacc[tb + t][3];
                }
            }
            __syncthreads();
            for (int idx = tid; idx < BLKR * 64; idx += NTH) {
                int nl = idx % BLKR, ol = idx / BLKR;
                int ng = blk * BLKR + nl;
                if (ng < NTOK) {
                    int o = oc * 64 + ol;
                    int i = ng / WSZ, j = ng - i * WSZ;
                    size_t gi = ((size_t)(b * CC + o) * HH + h0 + i) * HH + w0 + j;
                    out[gi] = x[gi] + out_s[nl * 65 + ol];
                }
            }
            __syncthreads();
        }
    }
}

// ---------------- launch ----------------
extern "C" void kernel_launch(void* const* d_in, const int* in_sizes, int n_in,
                              void* d_out, int out_size) {
    const float* x     = (const float*)d_in[0];
    const float* wt    = (const float*)d_in[1];
    const float* wp    = (const float*)d_in[2];
    const float* wproj = (const float*)d_in[3];
    float* out = (float*)d_out;

    cudaFuncSetAttribute(embed_kernel, cudaFuncAttributeMaxDynamicSharedMemorySize, EMBED_SMEM);
    cudaFuncSetAttribute(attn_kernel,  cudaFuncAttributeMaxDynamicSharedMemorySize, ATTN_SMEM);

    embed_kernel<<<NWIN, NTH, EMBED_SMEM>>>(x, wt, wp, wproj);
    attn_kernel<<<NWIN, NTH, ATTN_SMEM>>>(x, out);
}

// round 9
// speedup vs baseline: 2.5344x; 1.2189x over previous
#include <cuda_runtime.h>
#include <cuda_bf16.h>
#include <cstdint>

// Problem constants
#define NWIN 400
#define NTOK 324
#define NPAD 336    // 3 * 112, 7 * 48
#define CE   128
#define CC   256
#define HH   180
#define WSZ  18

#define BLKR  96    // token rows per block
#define NBLK  4
#define SCH   112   // S phi m-chunk
#define AVK   48    // AV k-chunk
#define NTH   384   // threads

// smem leading dims (elements); (ld/2) mod 32 in {4,12,28} -> ldmatrix tiles
// (8 rows x 16B) cover all 32 banks conflict-free
#define EMB_LD 264  // words 132, mod32=4
#define TH_LD  136  // words 68,  mod32=4
#define P_LD   344  // words 172, mod32=12
#define AV_LD  56   // words 28,  mod32=28
#define PJ_LD  136  // words 68,  mod32=4

// per-half ping-pong buffer; 2*CHUNK_HALF must hold proj staging [256][PJ_LD]=34816
#define CHUNK_HALF 17408

// ---------------- global scratch ----------------
__device__ __nv_bfloat16 g_embT [NWIN * NPAD * CC];  // [w][n][e]: e<128 theta, e>=128 phi
__device__ __nv_bfloat16 g_xw   [NWIN * CC * NPAD];  // [w][c][m]
__device__ __nv_bfloat16 g_wprojb[CC * CC];          // [o][c] (written by embed block 0)

// ---------------- helpers ----------------
__device__ __forceinline__ uint32_t s2u(const __nv_bfloat16* p) {
    return (uint32_t)__cvta_generic_to_shared(p);
}
__device__ __forceinline__ void ldsm4(uint32_t& r0, uint32_t& r1, uint32_t& r2, uint32_t& r3,
                                      uint32_t a) {
    asm volatile("ldmatrix.sync.aligned.m8n8.x4.shared.b16 {%0,%1,%2,%3}, [%4];"
        : "=r"(r0), "=r"(r1), "=r"(r2), "=r"(r3) : "r"(a));
}
__device__ __forceinline__ void ldsm2(uint32_t& r0, uint32_t& r1, uint32_t a) {
    asm volatile("ldmatrix.sync.aligned.m8n8.x2.shared.b16 {%0,%1}, [%2];"
        : "=r"(r0), "=r"(r1) : "r"(a));
}
__device__ __forceinline__ void mma16816(float* c, uint32_t a0, uint32_t a1,
                                         uint32_t a2, uint32_t a3,
                                         uint32_t b0, uint32_t b1) {
    asm volatile(
        "mma.sync.aligned.m16n8k16.row.col.f32.bf16.bf16.f32 "
        "{%0,%1,%2,%3},{%4,%5,%6,%7},{%8,%9},{%0,%1,%2,%3};\n"
        : "+f"(c[0]), "+f"(c[1]), "+f"(c[2]), "+f"(c[3])
        : "r"(a0), "r"(a1), "r"(a2), "r"(a3), "r"(b0), "r"(b1));
}
__device__ __forceinline__ void st_bf2(__nv_bfloat16* p, float lo, float hi) {
    *reinterpret_cast<__nv_bfloat162*>(p) = __floats2bfloat162_rn(lo, hi);
}
__device__ __forceinline__ void cp16(__nv_bfloat16* dst, const __nv_bfloat16* src) {
    *reinterpret_cast<uint4*>(dst) = *reinterpret_cast<const uint4*>(src);
}
__device__ __forceinline__ void cpasync16(__nv_bfloat16* smem_dst, const __nv_bfloat16* gsrc) {
    uint32_t s = (uint32_t)__cvta_generic_to_shared(smem_dst);
    asm volatile("cp.async.cg.shared.global [%0], [%1], 16;\n" :: "r"(s), "l"(gsrc));
}
#define CP_COMMIT() asm volatile("cp.async.commit_group;\n" ::: "memory")
#define CP_WAIT1()  asm volatile("cp.async.wait_group 1;\n" ::: "memory")
#define CP_WAIT0()  asm volatile("cp.async.wait_group 0;\n" ::: "memory")

// ---------------- kernel 1: window partition + embed GEMM (also preps wproj) ----
#define EMBED_SMEM ((CC * EMB_LD + BLKR * EMB_LD) * 2)

__global__ __launch_bounds__(NTH, 1) void embed_kernel(const float* __restrict__ x,
                                                       const float* __restrict__ wt,
                                                       const float* __restrict__ wp,
                                                       const float* __restrict__ wproj) {
    extern __shared__ char smem_raw[];
    __nv_bfloat16* wcomb_s = reinterpret_cast<__nv_bfloat16*>(smem_raw);   // [e][c]
    __nv_bfloat16* xwT_blk = wcomb_s + CC * EMB_LD;                        // [n][c]

    int w = blockIdx.x;
    int b = w / 100, rem = w % 100, wh = rem / 10, ww = rem % 10;
    int h0 = wh * WSZ, w0 = ww * WSZ;
    const float* xb = x + (size_t)b * CC * HH * HH;
    int tid = threadIdx.x;
    int warp = tid >> 5, lane = tid & 31;
    int rw = warp >> 1, cw = warp & 1;   // 6 row-groups x 2 col-halves
    int g = lane >> 2, q = lane & 3;
    int lA = lane & 15, kA = (lane >> 4) << 3;       // ldmatrix x4 lane pattern
    int lB = lane & 7,  kB = ((lane >> 3) & 1) << 3; // ldmatrix x2 lane pattern

    // block 0 additionally converts wproj -> g_wprojb (bf16) for the attn kernel
    if (blockIdx.x == 0) {
        for (int idx = tid; idx < CC * CC / 4; idx += NTH) {
            float4 f = *reinterpret_cast<const float4*>(&wproj[idx * 4]);
            __nv_bfloat162 lo = __floats2bfloat162_rn(f.x, f.y);
            __nv_bfloat162 hi = __floats2bfloat162_rn(f.z, f.w);
            uint2 v; v.x = *reinterpret_cast<uint32_t*>(&lo); v.y = *reinterpret_cast<uint32_t*>(&hi);
            *reinterpret_cast<uint2*>(&g_wprojb[idx * 4]) = v;
        }
    }

    // stage combined weight (convert float -> bf16), float4 loads
    for (int idx = tid; idx < CC * 64; idx += NTH) {
        int e = idx >> 6, v = idx & 63;
        const float* src = (e < CE) ? &wt[e * CC + v * 4] : &wp[(e - CE) * CC + v * 4];
        float4 f = *reinterpret_cast<const float4*>(src);
        __nv_bfloat162 lo = __floats2bfloat162_rn(f.x, f.y);
        __nv_bfloat162 hi = __floats2bfloat162_rn(f.z, f.w);
        uint2 o; o.x = *reinterpret_cast<uint32_t*>(&lo); o.y = *reinterpret_cast<uint32_t*>(&hi);
        *reinterpret_cast<uint2*>(&wcomb_s[e * EMB_LD + v * 4]) = o;
    }

    __nv_bfloat16* xwg  = g_xw   + (size_t)w * CC * NPAD;
    __nv_bfloat16* embT = g_embT + (size_t)w * NPAD * CC;
    __syncthreads();

    uint32_t aAdr = s2u(&xwT_blk[(rw * 16 + lA) * EMB_LD + kA]);
    uint32_t bAdr = s2u(&wcomb_s[(cw * 128 + lB) * EMB_LD + kB]);

    for (int blk = 0; blk < NBLK; blk++) {
        for (int idx = tid; idx < BLKR * CC; idx += NTH) {
            int nn = idx % BLKR, c = idx / BLKR;
            int m = blk * BLKR + nn;
            float v = 0.f;
            if (m < NTOK) {
                int i = m / WSZ, j = m - i * WSZ;
                v = xb[((size_t)c * HH + h0 + i) * HH + w0 + j];
            }
            __nv_bfloat16 bv = __float2bfloat16(v);
            xwT_blk[nn * EMB_LD + c] = bv;
            if (m < NPAD) xwg[c * NPAD + m] = bv;
        }
        __syncthreads();

        float acc[16][4];
        #pragma unroll
        for (int t = 0; t < 16; t++) { acc[t][0]=0.f; acc[t][1]=0.f; acc[t][2]=0.f; acc[t][3]=0.f; }
        #pragma unroll
        for (int kt = 0; kt < 16; kt++) {
            uint32_t a0, a1, a2, a3;
            ldsm4(a0, a1, a2, a3, aAdr + kt * 32);
            #pragma unroll
            for (int t = 0; t < 16; t++) {
                uint32_t b0, b1;
                ldsm2(b0, b1, bAdr + t * (8 * EMB_LD * 2) + kt * 32);
                mma16816(acc[t], a0, a1, a2, a3, b0, b1);
            }
        }
        {
            int r0 = blk * BLKR + rw * 16 + g, r1 = r0 + 8;
            #pragma unroll
            for (int t = 0; t < 16; t++) {
                int e0 = cw * 128 + t * 8 + q * 2;
                if (r0 < NPAD) st_bf2(&embT[r0 * CC + e0], acc[t][0], acc[t][1]);
                if (r1 < NPAD) st_bf2(&embT[r1 * CC + e0], acc[t][2], acc[t][3]);
            }
        }
        __syncthreads();
    }
}

// ---------------- kernel 2: fused attention + projection + residual ----------------
#define ATTN_SMEM ((BLKR*TH_LD + BLKR*P_LD + BLKR*EMB_LD + 2*CHUNK_HALF) * 2 + BLKR*2*4*2)

__global__ __launch_bounds__(NTH, 1) void attn_kernel(const float* __restrict__ x,
                                                      float* __restrict__ out) {
    extern __shared__ char smem_raw[];
    __nv_bfloat16* th_s  = reinterpret_cast<__nv_bfloat16*>(smem_raw);   // [n][e]
    __nv_bfloat16* P_s   = th_s + BLKR * TH_LD;                          // [n][m]
    __nv_bfloat16* y_s   = P_s + BLKR * P_LD;                            // [n][c]
    __nv_bfloat16* chunk = y_s + BLKR * EMB_LD;                          // 2 x CHUNK_HALF
    float* stats_max = reinterpret_cast<float*>(chunk + 2 * CHUNK_HALF);
    float* stats_sum = stats_max + BLKR * 2;
    float* out_s = reinterpret_cast<float*>(chunk);                      // fp32 [96][65]

    __nv_bfloat16* buf[2] = {chunk, chunk + CHUNK_HALF};

    int w = blockIdx.x;
    int b = w / 100, rem = w % 100, wh = rem / 10, ww = rem % 10;
    int h0 = wh * WSZ, w0 = ww * WSZ;
    int tid = threadIdx.x;
    int warp = tid >> 5, lane = tid & 31;
    int rw = warp >> 1, cw = warp & 1;   // 6 x 2
    int g = lane >> 2, q = lane & 3;
    int lA = lane & 15, kA = (lane >> 4) << 3;
    int lB = lane & 7,  kB = ((lane >> 3) & 1) << 3;

    const __nv_bfloat16* embT = g_embT + (size_t)w * NPAD * CC;
    const __nv_bfloat16* xwg  = g_xw   + (size_t)w * CC * NPAD;

    const float scale = 0.08838834764831845f;  // 1/sqrt(128)

    // precomputed ldmatrix base addresses (shared space)
    uint32_t aTh  = s2u(&th_s[(rw * 16 + lA) * TH_LD + kA]);
    uint32_t aP   = s2u(&P_s[(rw * 16 + lA) * P_LD + kA]);
    uint32_t aY   = s2u(&y_s[(rw * 16 + lA) * EMB_LD + kA]);
    uint32_t bPhi0 = s2u(&buf[0][(cw * 56 + lB) * TH_LD + kB]);
    uint32_t bPhi1 = s2u(&buf[1][(cw * 56 + lB) * TH_LD + kB]);
    uint32_t bAv0  = s2u(&buf[0][(cw * 128 + lB) * AV_LD + kB]);
    uint32_t bAv1  = s2u(&buf[1][(cw * 128 + lB) * AV_LD + kB]);
    uint32_t bPj   = s2u(&chunk[(cw * 128 + lB) * PJ_LD + kB]);

    for (int blk = 0; blk < NBLK; blk++) {
        // ---- prefetch phi chunk 0 (async), then stage theta rows ----
        for (int idx = tid; idx < SCH * 16; idx += NTH) {
            int mm = idx >> 4, v = idx & 15;
            cpasync16(&buf[0][mm * TH_LD + v * 8], &embT[mm * CC + CE + v * 8]);
        }
        CP_COMMIT();
        for (int idx = tid; idx < BLKR * 16; idx += NTH) {
            int r = idx >> 4, v = idx & 15;
            int ng = blk * BLKR + r;
            if (ng < NPAD) cp16(&th_s[r * TH_LD + v * 8], &embT[ng * CC + v * 8]);
            else *reinterpret_cast<uint4*>(&th_s[r * TH_LD + v * 8]) = make_uint4(0,0,0,0);
        }

        // ---- S = theta_blk @ phi^T (96x336), k=128, 3 double-buffered chunks ----
        float sacc[21][4];
        #pragma unroll
        for (int t = 0; t < 21; t++) { sacc[t][0]=0.f; sacc[t][1]=0.f; sacc[t][2]=0.f; sacc[t][3]=0.f; }
        for (int mc = 0; mc < 3; mc++) {
            if (mc < 2) {
                for (int idx = tid; idx < SCH * 16; idx += NTH) {
                    int mm = idx >> 4, v = idx & 15;
                    cpasync16(&buf[(mc + 1) & 1][mm * TH_LD + v * 8],
                              &embT[((mc + 1) * SCH + mm) * CC + CE + v * 8]);
                }
                CP_COMMIT();
                CP_WAIT1();
            } else {
                CP_WAIT0();
            }
            __syncthreads();
            uint32_t bPhi = (mc & 1) ? bPhi1 : bPhi0;
            #pragma unroll
            for (int kt = 0; kt < 8; kt++) {
                uint32_t a0, a1, a2, a3;
                ldsm4(a0, a1, a2, a3, aTh + kt * 32);
                #pragma unroll
                for (int t = 0; t < 7; t++) {
                    uint32_t b0, b1;
                    ldsm2(b0, b1, bPhi + t * (8 * TH_LD * 2) + kt * 32);
                    mma16816(sacc[mc * 7 + t], a0, a1, a2, a3, b0, b1);
                }
            }
            __syncthreads();
        }
        // ---- scale + column mask ----
        #pragma unroll
        for (int mc = 0; mc < 3; mc++) {
            #pragma unroll
            for (int t = 0; t < 7; t++) {
                int c0 = mc * SCH + cw * 56 + t * 8 + q * 2;
                float* sv = sacc[mc * 7 + t];
                #pragma unroll
                for (int i = 0; i < 4; i++) {
                    float v = sv[i] * scale;
                    int col = c0 + (i & 1);
                    if (col >= NTOK) v = -1e30f;
                    sv[i] = v;
                }
            }
        }
        // ---- row max ----
        float m0 = -1e30f, m1 = -1e30f;
        #pragma unroll
        for (int t = 0; t < 21; t++) {
            m0 = fmaxf(m0, fmaxf(sacc[t][0], sacc[t][1]));
            m1 = fmaxf(m1, fmaxf(sacc[t][2], sacc[t][3]));
        }
        m0 = fmaxf(m0, __shfl_xor_sync(0xffffffffu, m0, 1));
        m0 = fmaxf(m0, __shfl_xor_sync(0xffffffffu, m0, 2));
        m1 = fmaxf(m1, __shfl_xor_sync(0xffffffffu, m1, 1));
        m1 = fmaxf(m1, __shfl_xor_sync(0xffffffffu, m1, 2));
        int row0 = rw * 16 + g, row1 = row0 + 8;
        if (q == 0) { stats_max[row0 * 2 + cw] = m0; stats_max[row1 * 2 + cw] = m1; }
        __syncthreads();
        float rmax0 = fmaxf(stats_max[row0 * 2], stats_max[row0 * 2 + 1]);
        float rmax1 = fmaxf(stats_max[row1 * 2], stats_max[row1 * 2 + 1]);
        // ---- exp + row sums ----
        float s0 = 0.f, s1 = 0.f;
        #pragma unroll
        for (int t = 0; t < 21; t++) {
            sacc[t][0] = __expf(sacc[t][0] - rmax0);
            sacc[t][1] = __expf(sacc[t][1] - rmax0);
            sacc[t][2] = __expf(sacc[t][2] - rmax1);
            sacc[t][3] = __expf(sacc[t][3] - rmax1);
            s0 += sacc[t][0] + sacc[t][1];
            s1 += sacc[t][2] + sacc[t][3];
        }
        s0 += __shfl_xor_sync(0xffffffffu, s0, 1);
        s0 += __shfl_xor_sync(0xffffffffu, s0, 2);
        s1 += __shfl_xor_sync(0xffffffffu, s1, 1);
        s1 += __shfl_xor_sync(0xffffffffu, s1, 2);
        if (q == 0) { stats_sum[row0 * 2 + cw] = s0; stats_sum[row1 * 2 + cw] = s1; }
        __syncthreads();
        float inv0 = 1.f / (stats_sum[row0 * 2] + stats_sum[row0 * 2 + 1]);
        float inv1 = 1.f / (stats_sum[row1 * 2] + stats_sum[row1 * 2 + 1]);
        // ---- write normalized P ----
        #pragma unroll
        for (int mc = 0; mc < 3; mc++) {
            #pragma unroll
            for (int t = 0; t < 7; t++) {
                int c0 = mc * SCH + cw * 56 + t * 8 + q * 2;
                float* sv = sacc[mc * 7 + t];
                st_bf2(&P_s[row0 * P_LD + c0], sv[0] * inv0, sv[1] * inv0);
                st_bf2(&P_s[row1 * P_LD + c0], sv[2] * inv1, sv[3] * inv1);
            }
        }
        // prefetch AV chunk 0 (async); the loop's first barrier publishes P_s too
        for (int idx = tid; idx < CC * (AVK / 8); idx += NTH) {
            int c = idx / (AVK / 8), v = idx % (AVK / 8);
            cpasync16(&buf[0][c * AV_LD + v * 8], &xwg[c * NPAD + v * 8]);
        }
        CP_COMMIT();

        // ---- y = P @ xw^T (96x256), k=336 in 7 double-buffered chunks of 48 ----
        float yacc[16][4];
        #pragma unroll
        for (int t = 0; t < 16; t++) { yacc[t][0]=0.f; yacc[t][1]=0.f; yacc[t][2]=0.f; yacc[t][3]=0.f; }
        for (int mc = 0; mc < 7; mc++) {
            if (mc < 6) {
                for (int idx = tid; idx < CC * (AVK / 8); idx += NTH) {
                    int c = idx / (AVK / 8), v = idx % (AVK / 8);
                    cpasync16(&buf[(mc + 1) & 1][c * AV_LD + v * 8],
                              &xwg[c * NPAD + (mc + 1) * AVK + v * 8]);
                }
                CP_COMMIT();
                CP_WAIT1();
            } else {
                CP_WAIT0();
            }
            __syncthreads();
            uint32_t bAv = (mc & 1) ? bAv1 : bAv0;
            #pragma unroll
            for (int kt = 0; kt < 3; kt++) {
                uint32_t a0, a1, a2, a3;
                ldsm4(a0, a1, a2, a3, aP + (mc * AVK + kt * 16) * 2);
                #pragma unroll
                for (int t = 0; t < 16; t++) {
                    uint32_t b0, b1;
                    ldsm2(b0, b1, bAv + t * (8 * AV_LD * 2) + kt * 32);
                    mma16816(yacc[t], a0, a1, a2, a3, b0, b1);
                }
            }
            __syncthreads();
        }
        // ---- stage y (bf16) ----
        {
            int r0 = rw * 16 + g, r1 = r0 + 8;
            #pragma unroll
            for (int t = 0; t < 16; t++) {
                int c0 = cw * 128 + t * 8 + q * 2;
                st_bf2(&y_s[r0 * EMB_LD + c0], yacc[t][0], yacc[t][1]);
                st_bf2(&y_s[r1 * EMB_LD + c0], yacc[t][2], yacc[t][3]);
            }
        }
        __syncthreads();

        // ---- outp = y @ wproj^T (96x256), k=256 in 2 chunks of 128 ----
        float pacc[16][4];
        #pragma unroll
        for (int t = 0; t < 16; t++) { pacc[t][0]=0.f; pacc[t][1]=0.f; pacc[t][2]=0.f; pacc[t][3]=0.f; }
        for (int kc = 0; kc < 2; kc++) {
            for (int idx = tid; idx < CC * 16; idx += NTH) {
                int o = idx >> 4, v = idx & 15;
                cp16(&chunk[o * PJ_LD + v * 8], &g_wprojb[o * CC + kc * 128 + v * 8]);
            }
            __syncthreads();
            #pragma unroll
            for (int kt = 0; kt < 8; kt++) {
                uint32_t a0, a1, a2, a3;
                ldsm4(a0, a1, a2, a3, aY + (kc * 128 + kt * 16) * 2);
                #pragma unroll
                for (int t = 0; t < 16; t++) {
                    uint32_t b0, b1;
                    ldsm2(b0, b1, bPj + t * (8 * PJ_LD * 2) + kt * 32);
                    mma16816(pacc[t], a0, a1, a2, a3, b0, b1);
                }
            }
            __syncthreads();
        }

        // ---- epilogue: transpose via smem, residual add, coalesced write ----
        for (int oc = 0; oc < 4; oc++) {
            if ((oc >> 1) == cw) {
                int tb = (oc & 1) * 8;
                int r0 = rw * 16 + g, r1 = r0 + 8;
                #pragma unroll
                for (int t = 0; t < 8; t++) {
                    int cl = t * 8 + q * 2;
                    out_s[r0 * 65 + cl]     = pacc[tb + t][0];
                    out_s[r0 * 65 + cl + 1] = pacc[tb + t][1];
                    out_s[r1 * 65 + cl]     = pacc[tb + t][2];
                    out_s[r1 * 65 + cl + 1] = pacc[tb + t][3];
                }
            }
            __syncthreads();
            for (int idx = tid; idx < BLKR * 64; idx += NTH) {
                int nl = idx % BLKR, ol = idx / BLKR;
                int ng = blk * BLKR + nl;
                if (ng < NTOK) {
                    int o = oc * 64 + ol;
                    int i = ng / WSZ, j = ng - i * WSZ;
                    size_t gi = ((size_t)(b * CC + o) * HH + h0 + i) * HH + w0 + j;
                    out[gi] = x[gi] + out_s[nl * 65 + ol];
                }
            }
            __syncthreads();
        }
    }
}

// ---------------- launch ----------------
extern "C" void kernel_launch(void* const* d_in, const int* in_sizes, int n_in,
                              void* d_out, int out_size) {
    const float* x     = (const float*)d_in[0];
    const float* wt    = (const float*)d_in[1];
    const float* wp    = (const float*)d_in[2];
    const float* wproj = (const float*)d_in[3];
    float* out = (float*)d_out;

    cudaFuncSetAttribute(embed_kernel, cudaFuncAttributeMaxDynamicSharedMemorySize, EMBED_SMEM);
    cudaFuncSetAttribute(attn_kernel,  cudaFuncAttributeMaxDynamicSharedMemorySize, ATTN_SMEM);

    embed_kernel<<<NWIN, NTH, EMBED_SMEM>>>(x, wt, wp, wproj);
    attn_kernel<<<NWIN, NTH, ATTN_SMEM>>>(x, out);
}

// round 10
// speedup vs baseline: 3.5804x; 1.4127x over previous
#include <cuda_runtime.h>
#include <cuda_bf16.h>
#include <cstdint>

// Problem constants
#define NWIN 400
#define NTOK 324
#define NPAD 336    // 3 * 112, 7 * 48
#define CE   128
#define CC   256
#define HH   180
#define WSZ  18

#define BLKR  96    // attn token rows per block
#define NBLK  4
#define SCH   112   // S phi m-chunk
#define AVK   48    // AV k-chunk
#define NTH   384   // threads

#define EBR   48    // embed token rows per block
#define NBLK_E 7    // 48*7 = 336, no padding

// smem leading dims (elements); (ld/2) mod 32 in {4,12,28} -> ldmatrix tiles
// (8 rows x 16B) cover all 32 banks conflict-free
#define EMB_LD 264  // words 132, mod32=4
#define TH_LD  136  // words 68,  mod32=4
#define P_LD   344  // words 172, mod32=12
#define AV_LD  56   // words 28,  mod32=28
#define PJ_LD  136  // words 68,  mod32=4

// per-half ping-pong buffer; 2*CHUNK_HALF must hold proj staging [256][PJ_LD]=34816
// and the epilogue buffer fp32 [96][129] = 49536 B (34816*2*2 = 139264 B > 49536 OK)
#define CHUNK_HALF 17408

// ---------------- global scratch ----------------
__device__ __nv_bfloat16 g_embT [NWIN * NPAD * CC];  // [w][n][e]: e<128 theta, e>=128 phi
__device__ __nv_bfloat16 g_xw   [NWIN * CC * NPAD];  // [w][c][m]
__device__ __nv_bfloat16 g_wprojb[CC * CC];          // [o][c] (written by embed block 0)

// ---------------- helpers ----------------
__device__ __forceinline__ uint32_t s2u(const __nv_bfloat16* p) {
    return (uint32_t)__cvta_generic_to_shared(p);
}
__device__ __forceinline__ void ldsm4(uint32_t& r0, uint32_t& r1, uint32_t& r2, uint32_t& r3,
                                      uint32_t a) {
    asm volatile("ldmatrix.sync.aligned.m8n8.x4.shared.b16 {%0,%1,%2,%3}, [%4];"
        : "=r"(r0), "=r"(r1), "=r"(r2), "=r"(r3) : "r"(a));
}
__device__ __forceinline__ void ldsm2(uint32_t& r0, uint32_t& r1, uint32_t a) {
    asm volatile("ldmatrix.sync.aligned.m8n8.x2.shared.b16 {%0,%1}, [%2];"
        : "=r"(r0), "=r"(r1) : "r"(a));
}
__device__ __forceinline__ void mma16816(float* c, uint32_t a0, uint32_t a1,
                                         uint32_t a2, uint32_t a3,
                                         uint32_t b0, uint32_t b1) {
    asm volatile(
        "mma.sync.aligned.m16n8k16.row.col.f32.bf16.bf16.f32 "
        "{%0,%1,%2,%3},{%4,%5,%6,%7},{%8,%9},{%0,%1,%2,%3};\n"
        : "+f"(c[0]), "+f"(c[1]), "+f"(c[2]), "+f"(c[3])
        : "r"(a0), "r"(a1), "r"(a2), "r"(a3), "r"(b0), "r"(b1));
}
__device__ __forceinline__ void st_bf2(__nv_bfloat16* p, float lo, float hi) {
    *reinterpret_cast<__nv_bfloat162*>(p) = __floats2bfloat162_rn(lo, hi);
}
__device__ __forceinline__ void cp16(__nv_bfloat16* dst, const __nv_bfloat16* src) {
    *reinterpret_cast<uint4*>(dst) = *reinterpret_cast<const uint4*>(src);
}
__device__ __forceinline__ void cpasync16(__nv_bfloat16* smem_dst, const __nv_bfloat16* gsrc) {
    uint32_t s = (uint32_t)__cvta_generic_to_shared(smem_dst);
    asm volatile("cp.async.cg.shared.global [%0], [%1], 16;\n" :: "r"(s), "l"(gsrc));
}
#define CP_COMMIT() asm volatile("cp.async.commit_group;\n" ::: "memory")
#define CP_WAIT1()  asm volatile("cp.async.wait_group 1;\n" ::: "memory")
#define CP_WAIT0()  asm volatile("cp.async.wait_group 0;\n" ::: "memory")

// ---------------- kernel 1: window partition + embed GEMM (also preps wproj) ----
// smem: wcomb_s [256][EMB_LD] + 2 x xw buffer [48][EMB_LD]
#define EMBED_SMEM ((CC * EMB_LD + 2 * EBR * EMB_LD) * 2)

__global__ __launch_bounds__(NTH, 1) void embed_kernel(const float* __restrict__ x,
                                                       const float* __restrict__ wt,
                                                       const float* __restrict__ wp,
                                                       const float* __restrict__ wproj) {
    extern __shared__ char smem_raw[];
    __nv_bfloat16* wcomb_s = reinterpret_cast<__nv_bfloat16*>(smem_raw);   // [e][c]
    __nv_bfloat16* xb0 = wcomb_s + CC * EMB_LD;                            // [48][c]
    __nv_bfloat16* xb1 = xb0 + EBR * EMB_LD;

    int w = blockIdx.x;
    int b = w / 100, rem = w % 100, wh = rem / 10, ww = rem % 10;
    int h0 = wh * WSZ, w0 = ww * WSZ;
    const float* xb = x + (size_t)b * CC * HH * HH;
    int tid = threadIdx.x;
    int warp = tid >> 5, lane = tid & 31;
    int rw = warp >> 2, cw = warp & 3;   // 3 row-groups x 4 col-quarters
    int g = lane >> 2, q = lane & 3;
    int lA = lane & 15, kA = (lane >> 4) << 3;       // ldmatrix x4 lane pattern
    int lB = lane & 7,  kB = ((lane >> 3) & 1) << 3; // ldmatrix x2 lane pattern

    // block 0 additionally converts wproj -> g_wprojb (bf16) for the attn kernel
    if (blockIdx.x == 0) {
        for (int idx = tid; idx < CC * CC / 4; idx += NTH) {
            float4 f = *reinterpret_cast<const float4*>(&wproj[idx * 4]);
            __nv_bfloat162 lo = __floats2bfloat162_rn(f.x, f.y);
            __nv_bfloat162 hi = __floats2bfloat162_rn(f.z, f.w);
            uint2 v; v.x = *reinterpret_cast<uint32_t*>(&lo); v.y = *reinterpret_cast<uint32_t*>(&hi);
            *reinterpret_cast<uint2*>(&g_wprojb[idx * 4]) = v;
        }
    }

    // stage combined weight (convert float -> bf16), float4 loads
    for (int idx = tid; idx < CC * 64; idx += NTH) {
        int e = idx >> 6, v = idx & 63;
        const float* src = (e < CE) ? &wt[e * CC + v * 4] : &wp[(e - CE) * CC + v * 4];
        float4 f = *reinterpret_cast<const float4*>(src);
        __nv_bfloat162 lo = __floats2bfloat162_rn(f.x, f.y);
        __nv_bfloat162 hi = __floats2bfloat162_rn(f.z, f.w);
        uint2 o; o.x = *reinterpret_cast<uint32_t*>(&lo); o.y = *reinterpret_cast<uint32_t*>(&hi);
        *reinterpret_cast<uint2*>(&wcomb_s[e * EMB_LD + v * 4]) = o;
    }

    __nv_bfloat16* xwg  = g_xw   + (size_t)w * CC * NPAD;
    __nv_bfloat16* embT = g_embT + (size_t)w * NPAD * CC;

    // prologue: gather block 0 directly into xb0 (32 elems/thread)
    #pragma unroll
    for (int it = 0; it < 32; it++) {
        int idx = tid + it * NTH;
        int nn = idx % EBR, c = idx / EBR;
        int m = nn;  // blk 0
        float v = (m < NTOK) ? xb[((size_t)c * HH + h0 + m / WSZ) * HH + w0 + m % WSZ] : 0.f;
        __nv_bfloat16 bv = __float2bfloat16(v);
        xb0[nn * EMB_LD + c] = bv;
        xwg[c * NPAD + m] = bv;
    }
    __syncthreads();

    uint32_t aAdr[2] = { s2u(&xb0[(rw * 16 + lA) * EMB_LD + kA]),
                         s2u(&xb1[(rw * 16 + lA) * EMB_LD + kA]) };
    uint32_t bAdr = s2u(&wcomb_s[(cw * 64 + lB) * EMB_LD + kB]);

    for (int blk = 0; blk < NBLK_E; blk++) {
        // issue next block's gather loads (latency hidden under the GEMM)
        float vreg[32];
        if (blk + 1 < NBLK_E) {
            #pragma unroll
            for (int it = 0; it < 32; it++) {
                int idx = tid + it * NTH;
                int nn = idx % EBR, c = idx / EBR;
                int m = (blk + 1) * EBR + nn;
                vreg[it] = (m < NTOK) ? xb[((size_t)c * HH + h0 + m / WSZ) * HH + w0 + m % WSZ] : 0.f;
            }
        }

        // GEMM: [48][256] = xb @ wcomb^T, k=256
        float acc[8][4];
        #pragma unroll
        for (int t = 0; t < 8; t++) { acc[t][0]=0.f; acc[t][1]=0.f; acc[t][2]=0.f; acc[t][3]=0.f; }
        uint32_t aA = aAdr[blk & 1];
        #pragma unroll
        for (int kt = 0; kt < 16; kt++) {
            uint32_t a0, a1, a2, a3;
            ldsm4(a0, a1, a2, a3, aA + kt * 32);
            #pragma unroll
            for (int t = 0; t < 8; t++) {
                uint32_t b0, b1;
                ldsm2(b0, b1, bAdr + t * (8 * EMB_LD * 2) + kt * 32);
                mma16816(acc[t], a0, a1, a2, a3, b0, b1);
            }
        }
        // store token-major embeddings
        {
            int r0 = blk * EBR + rw * 16 + g, r1 = r0 + 8;
            #pragma unroll
            for (int t = 0; t < 8; t++) {
                int e0 = cw * 64 + t * 8 + q * 2;
                st_bf2(&embT[r0 * CC + e0], acc[t][0], acc[t][1]);
                st_bf2(&embT[r1 * CC + e0], acc[t][2], acc[t][3]);
            }
        }
        // convert + store next block into the other buffer, emit xwg
        if (blk + 1 < NBLK_E) {
            __nv_bfloat16* dst = (blk & 1) ? xb0 : xb1;
            #pragma unroll
            for (int it = 0; it < 32; it++) {
                int idx = tid + it * NTH;
                int nn = idx % EBR, c = idx / EBR;
                int m = (blk + 1) * EBR + nn;
                __nv_bfloat16 bv = __float2bfloat16(vreg[it]);
                dst[nn * EMB_LD + c] = bv;
                xwg[c * NPAD + m] = bv;
            }
        }
        __syncthreads();
    }
}

// ---------------- kernel 2: fused attention + projection + residual ----------------
#define ATTN_SMEM ((BLKR*TH_LD + BLKR*P_LD + BLKR*EMB_LD + 2*CHUNK_HALF) * 2 + BLKR*2*4*2)

__global__ __launch_bounds__(NTH, 1) void attn_kernel(const float* __restrict__ x,
                                                      float* __restrict__ out) {
    extern __shared__ char smem_raw[];
    __nv_bfloat16* th_s  = reinterpret_cast<__nv_bfloat16*>(smem_raw);   // [n][e]
    __nv_bfloat16* P_s   = th_s + BLKR * TH_LD;                          // [n][m]
    __nv_bfloat16* y_s   = P_s + BLKR * P_LD;                            // [n][c]
    __nv_bfloat16* chunk = y_s + BLKR * EMB_LD;                          // 2 x CHUNK_HALF
    float* stats_max = reinterpret_cast<float*>(chunk + 2 * CHUNK_HALF);
    float* stats_sum = stats_max + BLKR * 2;
    float* out_s = reinterpret_cast<float*>(chunk);                      // fp32 [96][129]

    __nv_bfloat16* buf[2] = {chunk, chunk + CHUNK_HALF};

    int w = blockIdx.x;
    int b = w / 100, rem = w % 100, wh = rem / 10, ww = rem % 10;
    int h0 = wh * WSZ, w0 = ww * WSZ;
    int tid = threadIdx.x;
    int warp = tid >> 5, lane = tid & 31;
    int rw = warp >> 1, cw = warp & 1;   // 6 x 2
    int g = lane >> 2, q = lane & 3;
    int lA = lane & 15, kA = (lane >> 4) << 3;
    int lB = lane & 7,  kB = ((lane >> 3) & 1) << 3;

    const __nv_bfloat16* embT = g_embT + (size_t)w * NPAD * CC;
    const __nv_bfloat16* xwg  = g_xw   + (size_t)w * CC * NPAD;

    const float scale = 0.08838834764831845f;  // 1/sqrt(128)

    // precomputed ldmatrix base addresses (shared space)
    uint32_t aTh  = s2u(&th_s[(rw * 16 + lA) * TH_LD + kA]);
    uint32_t aP   = s2u(&P_s[(rw * 16 + lA) * P_LD + kA]);
    uint32_t aY   = s2u(&y_s[(rw * 16 + lA) * EMB_LD + kA]);
    uint32_t bPhi0 = s2u(&buf[0][(cw * 56 + lB) * TH_LD + kB]);
    uint32_t bPhi1 = s2u(&buf[1][(cw * 56 + lB) * TH_LD + kB]);
    uint32_t bAv0  = s2u(&buf[0][(cw * 128 + lB) * AV_LD + kB]);
    uint32_t bAv1  = s2u(&buf[1][(cw * 128 + lB) * AV_LD + kB]);
    uint32_t bPj   = s2u(&chunk[(cw * 128 + lB) * PJ_LD + kB]);

    for (int blk = 0; blk < NBLK; blk++) {
        // ---- prefetch phi chunk 0 (async), then stage theta rows ----
        for (int idx = tid; idx < SCH * 16; idx += NTH) {
            int mm = idx >> 4, v = idx & 15;
            cpasync16(&buf[0][mm * TH_LD + v * 8], &embT[mm * CC + CE + v * 8]);
        }
        CP_COMMIT();
        for (int idx = tid; idx < BLKR * 16; idx += NTH) {
            int r = idx >> 4, v = idx & 15;
            int ng = blk * BLKR + r;
            if (ng < NPAD) cp16(&th_s[r * TH_LD + v * 8], &embT[ng * CC + v * 8]);
            else *reinterpret_cast<uint4*>(&th_s[r * TH_LD + v * 8]) = make_uint4(0,0,0,0);
        }

        // ---- S = theta_blk @ phi^T (96x336), k=128, 3 double-buffered chunks ----
        float sacc[21][4];
        #pragma unroll
        for (int t = 0; t < 21; t++) { sacc[t][0]=0.f; sacc[t][1]=0.f; sacc[t][2]=0.f; sacc[t][3]=0.f; }
        for (int mc = 0; mc < 3; mc++) {
            if (mc < 2) {
                for (int idx = tid; idx < SCH * 16; idx += NTH) {
                    int mm = idx >> 4, v = idx & 15;
                    cpasync16(&buf[(mc + 1) & 1][mm * TH_LD + v * 8],
                              &embT[((mc + 1) * SCH + mm) * CC + CE + v * 8]);
                }
                CP_COMMIT();
                CP_WAIT1();
            } else {
                CP_WAIT0();
            }
            __syncthreads();
            uint32_t bPhi = (mc & 1) ? bPhi1 : bPhi0;
            #pragma unroll
            for (int kt = 0; kt < 8; kt++) {
                uint32_t a0, a1, a2, a3;
                ldsm4(a0, a1, a2, a3, aTh + kt * 32);
                #pragma unroll
                for (int t = 0; t < 7; t++) {
                    uint32_t b0, b1;
                    ldsm2(b0, b1, bPhi + t * (8 * TH_LD * 2) + kt * 32);
                    mma16816(sacc[mc * 7 + t], a0, a1, a2, a3, b0, b1);
                }
            }
            __syncthreads();
        }
        // ---- scale + column mask ----
        #pragma unroll
        for (int mc = 0; mc < 3; mc++) {
            #pragma unroll
            for (int t = 0; t < 7; t++) {
                int c0 = mc * SCH + cw * 56 + t * 8 + q * 2;
                float* sv = sacc[mc * 7 + t];
                #pragma unroll
                for (int i = 0; i < 4; i++) {
                    float v = sv[i] * scale;
                    int col = c0 + (i & 1);
                    if (col >= NTOK) v = -1e30f;
                    sv[i] = v;
                }
            }
        }
        // ---- row max ----
        float m0 = -1e30f, m1 = -1e30f;
        #pragma unroll
        for (int t = 0; t < 21; t++) {
            m0 = fmaxf(m0, fmaxf(sacc[t][0], sacc[t][1]));
            m1 = fmaxf(m1, fmaxf(sacc[t][2], sacc[t][3]));
        }
        m0 = fmaxf(m0, __shfl_xor_sync(0xffffffffu, m0, 1));
        m0 = fmaxf(m0, __shfl_xor_sync(0xffffffffu, m0, 2));
        m1 = fmaxf(m1, __shfl_xor_sync(0xffffffffu, m1, 1));
        m1 = fmaxf(m1, __shfl_xor_sync(0xffffffffu, m1, 2));
        int row0 = rw * 16 + g, row1 = row0 + 8;
        if (q == 0) { stats_max[row0 * 2 + cw] = m0; stats_max[row1 * 2 + cw] = m1; }
        __syncthreads();
        float rmax0 = fmaxf(stats_max[row0 * 2], stats_max[row0 * 2 + 1]);
        float rmax1 = fmaxf(stats_max[row1 * 2], stats_max[row1 * 2 + 1]);
        // ---- exp + row sums ----
        float s0 = 0.f, s1 = 0.f;
        #pragma unroll
        for (int t = 0; t < 21; t++) {
            sacc[t][0] = __expf(sacc[t][0] - rmax0);
            sacc[t][1] = __expf(sacc[t][1] - rmax0);
            sacc[t][2] = __expf(sacc[t][2] - rmax1);
            sacc[t][3] = __expf(sacc[t][3] - rmax1);
            s0 += sacc[t][0] + sacc[t][1];
            s1 += sacc[t][2] + sacc[t][3];
        }
        s0 += __shfl_xor_sync(0xffffffffu, s0, 1);
        s0 += __shfl_xor_sync(0xffffffffu, s0, 2);
        s1 += __shfl_xor_sync(0xffffffffu, s1, 1);
        s1 += __shfl_xor_sync(0xffffffffu, s1, 2);
        if (q == 0) { stats_sum[row0 * 2 + cw] = s0; stats_sum[row1 * 2 + cw] = s1; }
        __syncthreads();
        float inv0 = 1.f / (stats_sum[row0 * 2] + stats_sum[row0 * 2 + 1]);
        float inv1 = 1.f / (stats_sum[row1 * 2] + stats_sum[row1 * 2 + 1]);
        // ---- write normalized P ----
        #pragma unroll
        for (int mc = 0; mc < 3; mc++) {
            #pragma unroll
            for (int t = 0; t < 7; t++) {
                int c0 = mc * SCH + cw * 56 + t * 8 + q * 2;
                float* sv = sacc[mc * 7 + t];
                st_bf2(&P_s[row0 * P_LD + c0], sv[0] * inv0, sv[1] * inv0);
                st_bf2(&P_s[row1 * P_LD + c0], sv[2] * inv1, sv[3] * inv1);
            }
        }
        // prefetch AV chunk 0 (async); the loop's first barrier publishes P_s too
        for (int idx = tid; idx < CC * (AVK / 8); idx += NTH) {
            int c = idx / (AVK / 8), v = idx % (AVK / 8);
            cpasync16(&buf[0][c * AV_LD + v * 8], &xwg[c * NPAD + v * 8]);
        }
        CP_COMMIT();

        // ---- y = P @ xw^T (96x256), k=336 in 7 double-buffered chunks of 48 ----
        float yacc[16][4];
        #pragma unroll
        for (int t = 0; t < 16; t++) { yacc[t][0]=0.f; yacc[t][1]=0.f; yacc[t][2]=0.f; yacc[t][3]=0.f; }
        for (int mc = 0; mc < 7; mc++) {
            if (mc < 6) {
                for (int idx = tid; idx < CC * (AVK / 8); idx += NTH) {
                    int c = idx / (AVK / 8), v = idx % (AVK / 8);
                    cpasync16(&buf[(mc + 1) & 1][c * AV_LD + v * 8],
                              &xwg[c * NPAD + (mc + 1) * AVK + v * 8]);
                }
                CP_COMMIT();
                CP_WAIT1();
            } else {
                CP_WAIT0();
            }
            __syncthreads();
            uint32_t bAv = (mc & 1) ? bAv1 : bAv0;
            #pragma unroll
            for (int kt = 0; kt < 3; kt++) {
                uint32_t a0, a1, a2, a3;
                ldsm4(a0, a1, a2, a3, aP + (mc * AVK + kt * 16) * 2);
                #pragma unroll
                for (int t = 0; t < 16; t++) {
                    uint32_t b0, b1;
                    ldsm2(b0, b1, bAv + t * (8 * AV_LD * 2) + kt * 32);
                    mma16816(yacc[t], a0, a1, a2, a3, b0, b1);
                }
            }
            __syncthreads();
        }
        // ---- stage y (bf16) ----
        {
            int r0 = rw * 16 + g, r1 = r0 + 8;
            #pragma unroll
            for (int t = 0; t < 16; t++) {
                int c0 = cw * 128 + t * 8 + q * 2;
                st_bf2(&y_s[r0 * EMB_LD + c0], yacc[t][0], yacc[t][1]);
                st_bf2(&y_s[r1 * EMB_LD + c0], yacc[t][2], yacc[t][3]);
            }
        }
        __syncthreads();

        // ---- outp = y @ wproj^T (96x256), k=256 in 2 chunks of 128 ----
        float pacc[16][4];
        #pragma unroll
        for (int t = 0; t < 16; t++) { pacc[t][0]=0.f; pacc[t][1]=0.f; pacc[t][2]=0.f; pacc[t][3]=0.f; }
        for (int kc = 0; kc < 2; kc++) {
            for (int idx = tid; idx < CC * 16; idx += NTH) {
                int o = idx >> 4, v = idx & 15;
                cp16(&chunk[o * PJ_LD + v * 8], &g_wprojb[o * CC + kc * 128 + v * 8]);
            }
            __syncthreads();
            #pragma unroll
            for (int kt = 0; kt < 8; kt++) {
                uint32_t a0, a1, a2, a3;
                ldsm4(a0, a1, a2, a3, aY + (kc * 128 + kt * 16) * 2);
                #pragma unroll
                for (int t = 0; t < 16; t++) {
                    uint32_t b0, b1;
                    ldsm2(b0, b1, bPj + t * (8 * PJ_LD * 2) + kt * 32);
                    mma16816(pacc[t], a0, a1, a2, a3, b0, b1);
                }
            }
            __syncthreads();
        }

        // ---- epilogue: 2 passes, all warps active, [96][129] fp32 transpose buffer ----
        for (int p = 0; p < 2; p++) {
            int tb = p * 8;
            int r0 = rw * 16 + g, r1 = r0 + 8;
            #pragma unroll
            for (int tl = 0; tl < 8; tl++) {
                int cc = cw * 64 + tl * 8 + q * 2;
                out_s[r0 * 129 + cc]     = pacc[tb + tl][0];
                out_s[r0 * 129 + cc + 1] = pacc[tb + tl][1];
                out_s[r1 * 129 + cc]     = pacc[tb + tl][2];
                out_s[r1 * 129 + cc + 1] = pacc[tb + tl][3];
            }
            __syncthreads();
            for (int idx = tid; idx < BLKR * 128; idx += NTH) {
                int nl = idx % BLKR, ol = idx / BLKR;
                int ng = blk * BLKR + nl;
                if (ng < NTOK) {
                    int o = ol + (ol & 64) + p * 64;   // cw=0 cols | cw=1 cols
                    int i = ng / WSZ, j = ng - i * WSZ;
                    size_t gi = ((size_t)(b * CC + o) * HH + h0 + i) * HH + w0 + j;
                    out[gi] = x[gi] + out_s[nl * 129 + ol];
                }
            }
            __syncthreads();
        }
    }
}

// ---------------- launch ----------------
extern "C" void kernel_launch(void* const* d_in, const int* in_sizes, int n_in,
                              void* d_out, int out_size) {
    const float* x     = (const float*)d_in[0];
    const float* wt    = (const float*)d_in[1];
    const float* wp    = (const float*)d_in[2];
    const float* wproj = (const float*)d_in[3];
    float* out = (float*)d_out;

    cudaFuncSetAttribute(embed_kernel, cudaFuncAttributeMaxDynamicSharedMemorySize, EMBED_SMEM);
    cudaFuncSetAttribute(attn_kernel,  cudaFuncAttributeMaxDynamicSharedMemorySize, ATTN_SMEM);

    embed_kernel<<<NWIN, NTH, EMBED_SMEM>>>(x, wt, wp, wproj);
    attn_kernel<<<NWIN, NTH, ATTN_SMEM>>>(x, out);
}